// round 3
// baseline (speedup 1.0000x reference)
#include <cuda_runtime.h>
#include <math.h>

#define NN 100000
#define NE 400000
#define IND 771
#define HID 256
#define NG 64

// ---------------- scratch (static device globals; no allocation) ----------------
__device__ float  g_ylr[(size_t)NN * 512];   // [yl | yr] per node
__device__ float  g_m[(size_t)NN * 256];     // scatter accumulator, then pre-BN
__device__ float  g_h[(size_t)NN * 256];     // layer output
__device__ float  g_deg[NN];
__device__ float  g_inv[NN];
__device__ float  g_WB[IND * 512];           // packed [Wl | Wr]
__device__ double g_sum[256];
__device__ double g_sumsq[256];
__device__ float  g_scale[256];
__device__ float  g_shift[256];
__device__ float  g_s[NN];
__device__ float  g_w[NN];                   // e then w
__device__ float  g_smax[NG];
__device__ float  g_denom[NG];
__device__ float  g_pooled[NG * HID];
// normalized int32 indices (robust to int32-vs-int64 input dtype)
__device__ int    g_is64;
__device__ int    g_src[NE];
__device__ int    g_dst[NE];
__device__ int    g_batch[NN];

// ---------------- helpers ----------------
__device__ __forceinline__ void atomicMaxFloat(float* addr, float val) {
    int* ai = (int*)addr;
    int old = __float_as_int(*addr);
    while (__int_as_float(old) < val) {
        int assumed = old;
        old = atomicCAS(ai, assumed, __float_as_int(val));
        if (old == assumed) break;
    }
}

// ---------------- dtype detection + index normalization ----------------
// If the 800000-element edge_index buffer is int32 but read as u64, values are
// (hi<<32)|lo with hi a random node id > 0 almost surely -> huge. True int64
// values are all < NN.
__global__ void detect_dtype(const unsigned long long* __restrict__ ei) {
    if (threadIdx.x == 0 && blockIdx.x == 0) {
        int is64 = 1;
        for (int i = 0; i < 64; i++)
            if (ei[i] >= (unsigned long long)NN) { is64 = 0; break; }
        g_is64 = is64;
    }
}
__global__ void cvt_edges(const void* __restrict__ ei) {
    int e = blockIdx.x * blockDim.x + threadIdx.x;
    if (e >= NE) return;
    if (g_is64) {
        const long long* p = (const long long*)ei;
        g_src[e] = (int)p[e];
        g_dst[e] = (int)p[NE + e];
    } else {
        const int* p = (const int*)ei;
        g_src[e] = p[e];
        g_dst[e] = p[NE + e];
    }
}
__global__ void cvt_batch(const void* __restrict__ b) {
    int n = blockIdx.x * blockDim.x + threadIdx.x;
    if (n >= NN) return;
    if (g_is64) g_batch[n] = (int)((const long long*)b)[n];
    else        g_batch[n] = ((const int*)b)[n];
}

// ---------------- zero / init kernels ----------------
__global__ void zero_m() {
    size_t i = (size_t)blockIdx.x * blockDim.x + threadIdx.x;
    if (i < (size_t)NN * 64) ((float4*)g_m)[i] = make_float4(0.f, 0.f, 0.f, 0.f);
}
__global__ void zero_deg() {
    int i = blockIdx.x * blockDim.x + threadIdx.x;
    if (i < NN) g_deg[i] = 0.f;
}
__global__ void zero_stats() {
    int c = threadIdx.x;
    g_sum[c] = 0.0; g_sumsq[c] = 0.0;
}
__global__ void init_pool() {
    int i = blockIdx.x * blockDim.x + threadIdx.x;
    if (i < NG * HID) g_pooled[i] = 0.f;
    if (i < NG) { g_smax[i] = -3.4e38f; g_denom[i] = 0.f; }
}
__global__ void init_s(const float* __restrict__ ba2) {
    int n = blockIdx.x * blockDim.x + threadIdx.x;
    if (n < NN) g_s[n] = ba2[0];
}

// ---------------- degree ----------------
__global__ void deg_kernel() {
    int e = blockIdx.x * blockDim.x + threadIdx.x;
    if (e < NE) atomicAdd(&g_deg[g_dst[e]], 1.f);
}
__global__ void inv_kernel() {
    int n = blockIdx.x * blockDim.x + threadIdx.x;
    if (n < NN) g_inv[n] = 1.f / fmaxf(g_deg[n], 1.f);
}

// ---------------- pack [Wl | Wr] into K x 512 ----------------
__global__ void pack_wb(const float* __restrict__ Wl, const float* __restrict__ Wr, int K) {
    int i = blockIdx.x * blockDim.x + threadIdx.x;
    if (i >= K * 256) return;
    int k = i >> 8, c = i & 255;
    g_WB[k * 512 + c]       = Wl[i];
    g_WB[k * 512 + 256 + c] = Wr[i];
}

// ---------------- fp32 tiled GEMM: g_ylr[M x 512] = A[M x K] @ g_WB[K x 512] ----------------
__global__ __launch_bounds__(256) void sgemm512(const float* __restrict__ A_ext, int use_h,
                                                int K, int lda) {
    const float* __restrict__ A = use_h ? g_h : A_ext;
    __shared__ float As[8][128];
    __shared__ float Bs[8][128];
    int tid  = threadIdx.x;
    int row0 = blockIdx.y * 128, col0 = blockIdx.x * 128;
    int tx = tid & 15, ty = tid >> 4;
    int a_r = tid >> 1, a_k = (tid & 1) * 4;
    int b_k = tid >> 5, b_c = (tid & 31) * 4;

    float acc[8][8];
#pragma unroll
    for (int i = 0; i < 8; i++)
#pragma unroll
        for (int j = 0; j < 8; j++) acc[i][j] = 0.f;

    for (int k0 = 0; k0 < K; k0 += 8) {
        int ar = row0 + a_r;
#pragma unroll
        for (int i = 0; i < 4; i++) {
            int k = k0 + a_k + i;
            As[a_k + i][a_r] = (ar < NN && k < K) ? __ldg(A + (size_t)ar * lda + k) : 0.f;
        }
        {
            int kb = k0 + b_k;
            float4 bv = make_float4(0.f, 0.f, 0.f, 0.f);
            if (kb < K) bv = *(const float4*)(g_WB + (size_t)kb * 512 + col0 + b_c);
            *(float4*)&Bs[b_k][b_c] = bv;
        }
        __syncthreads();
#pragma unroll
        for (int kk = 0; kk < 8; kk++) {
            float4 a0 = *(const float4*)&As[kk][ty * 8];
            float4 a1 = *(const float4*)&As[kk][ty * 8 + 4];
            float4 b0 = *(const float4*)&Bs[kk][tx * 8];
            float4 b1 = *(const float4*)&Bs[kk][tx * 8 + 4];
            float ar8[8] = {a0.x, a0.y, a0.z, a0.w, a1.x, a1.y, a1.z, a1.w};
            float br8[8] = {b0.x, b0.y, b0.z, b0.w, b1.x, b1.y, b1.z, b1.w};
#pragma unroll
            for (int i = 0; i < 8; i++)
#pragma unroll
                for (int j = 0; j < 8; j++) acc[i][j] += ar8[i] * br8[j];
        }
        __syncthreads();
    }
#pragma unroll
    for (int i = 0; i < 8; i++) {
        int r = row0 + ty * 8 + i;
        if (r < NN) {
            float4 v0 = make_float4(acc[i][0], acc[i][1], acc[i][2], acc[i][3]);
            float4 v1 = make_float4(acc[i][4], acc[i][5], acc[i][6], acc[i][7]);
            *(float4*)(g_ylr + (size_t)r * 512 + col0 + tx * 8)     = v0;
            *(float4*)(g_ylr + (size_t)r * 512 + col0 + tx * 8 + 4) = v1;
        }
    }
}

// ---------------- edge scatter: g_m[dst] += yl part of g_ylr[src] ----------------
__global__ void scatter_kernel() {
    int e = blockIdx.x * 4 + (threadIdx.x >> 6);
    if (e >= NE) return;
    int c   = (threadIdx.x & 63) * 4;
    int src = g_src[e];
    int dst = g_dst[e];
    float4 v = *(const float4*)(g_ylr + (size_t)src * 512 + c);
    float* mp = g_m + (size_t)dst * 256 + c;
    atomicAdd(mp + 0, v.x);
    atomicAdd(mp + 1, v.y);
    atomicAdd(mp + 2, v.z);
    atomicAdd(mp + 3, v.w);
}

// ---------------- combine + BN stats: pre = m*inv + bl + yr (in-place to g_m) ----------------
__global__ void combine_stats(const float* __restrict__ bl) {
    int c  = threadIdx.x;
    int r0 = blockIdx.x * 256;
    int r1 = min(r0 + 256, NN);
    float bias = bl[c];
    float s = 0.f, s2 = 0.f;
    for (int r = r0; r < r1; r++) {
        float pre = g_m[(size_t)r * 256 + c] * g_inv[r] + bias + g_ylr[(size_t)r * 512 + 256 + c];
        g_m[(size_t)r * 256 + c] = pre;
        s += pre; s2 += pre * pre;
    }
    atomicAdd(&g_sum[c], (double)s);
    atomicAdd(&g_sumsq[c], (double)s2);
}

__global__ void finalize_bn(const float* __restrict__ gm, const float* __restrict__ bt) {
    int c = threadIdx.x;
    double mean = g_sum[c] / (double)NN;
    double var  = g_sumsq[c] / (double)NN - mean * mean;
    float rstd  = rsqrtf((float)var + 1e-5f);
    float sc    = rstd * gm[c];
    g_scale[c]  = sc;
    g_shift[c]  = bt[c] - (float)mean * sc;
}

__global__ void bnrelu() {
    size_t i = (size_t)blockIdx.x * blockDim.x + threadIdx.x;
    if (i >= (size_t)NN * 64) return;
    size_t idx = i * 4;
    int c = (int)(idx & 255);
    float4 v = *(const float4*)(g_m + idx);
    v.x = fmaxf(v.x * g_scale[c + 0] + g_shift[c + 0], 0.f);
    v.y = fmaxf(v.y * g_scale[c + 1] + g_shift[c + 1], 0.f);
    v.z = fmaxf(v.z * g_scale[c + 2] + g_shift[c + 2], 0.f);
    v.w = fmaxf(v.w * g_scale[c + 3] + g_shift[c + 3], 0.f);
    *(float4*)(g_h + idx) = v;
}

// ---------------- attention score (j-split, static 40KB smem):
//   g_s[n] += sum_{j in block's 32 cols} tanh(h[n]·Wa1[:,j] + ba1[j]) * Wa2[j]
__global__ __launch_bounds__(256) void score_kernel(const float* __restrict__ Wa1,
                                                    const float* __restrict__ ba1,
                                                    const float* __restrict__ Wa2) {
    __shared__ float Wa1s[256 * 32];  // 32 KB slice: Wa1[:, jblk*32 .. +32)
    __shared__ float hrow[8 * 256];   // 8 KB: 8 node rows
    int jblk = blockIdx.x;            // 0..3
    int tid  = threadIdx.x;
    for (int i = tid; i < 256 * 32; i += 256) {
        int k = i >> 5, jj = i & 31;
        Wa1s[i] = Wa1[k * 128 + jblk * 32 + jj];
    }
    int jj = tid & 31, nd = tid >> 5;
    int j  = jblk * 32 + jj;
    float b1 = ba1[j], w2 = Wa2[j];
    __syncthreads();
    for (int n0 = blockIdx.y * 8; n0 < NN; n0 += gridDim.y * 8) {
        __syncthreads();
        // stage 8 rows x 256 floats = 512 float4
        for (int i = tid; i < 512; i += 256) {
            int r = n0 + (i >> 6);
            float4 v = (r < NN) ? *(const float4*)(g_h + (size_t)r * 256 + (size_t)(i & 63) * 4)
                                : make_float4(0.f, 0.f, 0.f, 0.f);
            *(float4*)&hrow[i * 4] = v;
        }
        __syncthreads();
        int n = n0 + nd;
        float acc = b1;
        const float* hp = hrow + nd * 256;
#pragma unroll 8
        for (int k = 0; k < 256; k++) acc += hp[k] * Wa1s[k * 32 + jj];
        float t = tanhf(acc) * w2;
#pragma unroll
        for (int o = 16; o; o >>= 1) t += __shfl_down_sync(0xffffffffu, t, o);
        if (jj == 0 && n < NN) atomicAdd(&g_s[n], t);
    }
}

// ---------------- per-graph softmax ----------------
__global__ void segmax_kernel() {
    int n  = blockIdx.x * blockDim.x + threadIdx.x;
    int nc = min(n, NN - 1);
    int g  = g_batch[nc];
    float v = (n < NN) ? g_s[n] : -3.4e38f;
    int g0 = __shfl_sync(0xffffffffu, g, 0);
    bool uni = __all_sync(0xffffffffu, g == g0);
    if (uni) {
#pragma unroll
        for (int o = 16; o; o >>= 1) v = fmaxf(v, __shfl_down_sync(0xffffffffu, v, o));
        if ((threadIdx.x & 31) == 0) atomicMaxFloat(&g_smax[g0], v);
    } else if (n < NN) {
        atomicMaxFloat(&g_smax[g], v);
    }
}

__global__ void expsum_kernel() {
    int n  = blockIdx.x * blockDim.x + threadIdx.x;
    int nc = min(n, NN - 1);
    int g  = g_batch[nc];
    float e = 0.f;
    if (n < NN) { e = expf(g_s[n] - g_smax[g]); g_w[n] = e; }
    int g0 = __shfl_sync(0xffffffffu, g, 0);
    bool uni = __all_sync(0xffffffffu, g == g0);
    if (uni) {
#pragma unroll
        for (int o = 16; o; o >>= 1) e += __shfl_down_sync(0xffffffffu, e, o);
        if ((threadIdx.x & 31) == 0) atomicAdd(&g_denom[g0], e);
    } else if (n < NN) {
        atomicAdd(&g_denom[g], e);
    }
}

__global__ void weights_kernel() {
    int n = blockIdx.x * blockDim.x + threadIdx.x;
    if (n < NN) g_w[n] = g_w[n] / g_denom[g_batch[n]];
}

// ---------------- weighted pooling (sorted batch -> running flush) ----------------
__global__ void pooled_kernel() {
    int c  = threadIdx.x;  // 256
    int r0 = blockIdx.x * 512;
    if (r0 >= NN) return;
    int r1  = min(r0 + 512, NN);
    int cur = g_batch[r0];
    float acc = 0.f;
    for (int r = r0; r < r1; r++) {
        int g = g_batch[r];
        if (g != cur) { atomicAdd(&g_pooled[cur * 256 + c], acc); acc = 0.f; cur = g; }
        acc += g_h[(size_t)r * 256 + c] * g_w[r];
    }
    atomicAdd(&g_pooled[cur * 256 + c], acc);
}

// ---------------- classifier ----------------
__global__ void classifier_kernel(const float* __restrict__ Wc1, const float* __restrict__ bc1,
                                  const float* __restrict__ Wc2, const float* __restrict__ bc2,
                                  float* __restrict__ out) {
    int g = blockIdx.x;   // 64
    int j = threadIdx.x;  // 128
    float acc = bc1[j];
    for (int k = 0; k < 256; k++) acc += g_pooled[g * 256 + k] * Wc1[k * 128 + j];
    float t = fmaxf(acc, 0.f) * Wc2[j];
#pragma unroll
    for (int o = 16; o; o >>= 1) t += __shfl_down_sync(0xffffffffu, t, o);
    __shared__ float red[4];
    if ((j & 31) == 0) red[j >> 5] = t;
    __syncthreads();
    if (j == 0) out[g] = red[0] + red[1] + red[2] + red[3] + bc2[0];
}

// ---------------- launch ----------------
extern "C" void kernel_launch(void* const* d_in, const int* in_sizes, int n_in,
                              void* d_out, int out_size) {
    const float* x     = (const float*)d_in[0];
    const void*  ei    = d_in[1];
    const void*  batch = d_in[2];
    const float* Wl[3] = {(const float*)d_in[3], (const float*)d_in[8],  (const float*)d_in[13]};
    const float* bl[3] = {(const float*)d_in[4], (const float*)d_in[9],  (const float*)d_in[14]};
    const float* Wr[3] = {(const float*)d_in[5], (const float*)d_in[10], (const float*)d_in[15]};
    const float* gg[3] = {(const float*)d_in[6], (const float*)d_in[11], (const float*)d_in[16]};
    const float* bb[3] = {(const float*)d_in[7], (const float*)d_in[12], (const float*)d_in[17]};
    const float* Wa1 = (const float*)d_in[18];
    const float* ba1 = (const float*)d_in[19];
    const float* Wa2 = (const float*)d_in[20];
    const float* ba2 = (const float*)d_in[21];
    const float* Wc1 = (const float*)d_in[22];
    const float* bc1 = (const float*)d_in[23];
    const float* Wc2 = (const float*)d_in[24];
    const float* bc2 = (const float*)d_in[25];
    float* out = (float*)d_out;

    // normalize index dtype (int32 vs int64) once
    detect_dtype<<<1, 32>>>((const unsigned long long*)ei);
    cvt_edges<<<(NE + 255) / 256, 256>>>(ei);
    cvt_batch<<<(NN + 255) / 256, 256>>>(batch);

    // degree (once; same for all layers)
    zero_deg<<<(NN + 255) / 256, 256>>>();
    deg_kernel<<<(NE + 255) / 256, 256>>>();
    inv_kernel<<<(NN + 255) / 256, 256>>>();

    for (int L = 0; L < 3; L++) {
        int K     = (L == 0) ? IND : HID;
        int use_h = (L == 0) ? 0 : 1;
        pack_wb<<<(K * 256 + 255) / 256, 256>>>(Wl[L], Wr[L], K);
        dim3 grid(4, (NN + 127) / 128);
        sgemm512<<<grid, 256>>>(x, use_h, K, K);
        zero_m<<<(NN * 64 + 255) / 256, 256>>>();
        scatter_kernel<<<(NE + 3) / 4, 256>>>();
        zero_stats<<<1, 256>>>();
        combine_stats<<<(NN + 255) / 256, 256>>>(bl[L]);
        finalize_bn<<<1, 256>>>(gg[L], bb[L]);
        bnrelu<<<(NN * 64 + 255) / 256, 256>>>();
    }

    init_s<<<(NN + 255) / 256, 256>>>(ba2);
    {
        dim3 sgrid(4, 592);
        score_kernel<<<sgrid, 256>>>(Wa1, ba1, Wa2);
    }
    init_pool<<<(NG * HID + 255) / 256, 256>>>();
    segmax_kernel<<<(NN + 255) / 256, 256>>>();
    expsum_kernel<<<(NN + 255) / 256, 256>>>();
    weights_kernel<<<(NN + 255) / 256, 256>>>();
    pooled_kernel<<<(NN + 511) / 512, 256>>>();
    classifier_kernel<<<NG, 128>>>(Wc1, bc1, Wc2, bc2, out);
}

// round 5
// speedup vs baseline: 1.6496x; 1.6496x over previous
#include <cuda_runtime.h>
#include <cuda_bf16.h>
#include <math.h>
#include <stdint.h>

#define NN 100000
#define NE 400000
#define IND 771
#define HID 256
#define NG 64
#define KP0 800   // padded K for layer 0 (25 chunks of 32)

// ---------------- scratch (static device globals; no allocation) ----------------
__device__ float  g_ylr[(size_t)NN * 512];   // [yl | yr] per node
__device__ float  g_m[(size_t)NN * 256];     // scatter accumulator, then pre-BN
__device__ float  g_h[(size_t)NN * 256];     // layer output
__device__ float  g_deg[NN];
__device__ float  g_inv[NN];
__device__ double g_sum[256];
__device__ double g_sumsq[256];
__device__ float  g_scale[256];
__device__ float  g_shift[256];
__device__ float  g_s[NN];
__device__ float  g_w[NN];
__device__ float  g_smax[NG];
__device__ float  g_denom[NG];
__device__ float  g_pooled[NG * HID];
__device__ int    g_is64;
__device__ int    g_src[NE];
__device__ int    g_dst[NE];
__device__ int    g_batch[NN];
// bf16 split operands for tensor-core GEMM
__device__ __nv_bfloat16 g_ah[(size_t)NN * KP0];
__device__ __nv_bfloat16 g_al[(size_t)NN * KP0];
__device__ __nv_bfloat16 g_bh[512 * KP0];
__device__ __nv_bfloat16 g_bl[512 * KP0];

// ---------------- helpers ----------------
__device__ __forceinline__ uint32_t smem_u32(const void* p) {
    uint32_t a;
    asm("{ .reg .u64 t; cvta.to.shared.u64 t, %1; cvt.u32.u64 %0, t; }" : "=r"(a) : "l"(p));
    return a;
}
// conflict-free swizzle for 64B rows of 16B segments
#define SWZ(b) ((b) ^ ((((b) >> 7) & 3) << 4))

__device__ __forceinline__ void sts128(uint32_t addr, float4 v) {
    asm volatile("st.shared.v4.b32 [%0], {%1,%2,%3,%4};"
                 :: "r"(addr), "r"(__float_as_uint(v.x)), "r"(__float_as_uint(v.y)),
                    "r"(__float_as_uint(v.z)), "r"(__float_as_uint(v.w)) : "memory");
}
__device__ __forceinline__ void ldsm4(uint32_t* r, uint32_t addr) {
    asm volatile("ldmatrix.sync.aligned.m8n8.x4.shared.b16 {%0,%1,%2,%3}, [%4];"
                 : "=r"(r[0]), "=r"(r[1]), "=r"(r[2]), "=r"(r[3]) : "r"(addr));
}
__device__ __forceinline__ void mma_bf16(float* c, const uint32_t* a, uint32_t b0, uint32_t b1) {
    asm volatile(
        "mma.sync.aligned.m16n8k16.row.col.f32.bf16.bf16.f32 "
        "{%0,%1,%2,%3}, {%4,%5,%6,%7}, {%8,%9}, {%0,%1,%2,%3};"
        : "+f"(c[0]), "+f"(c[1]), "+f"(c[2]), "+f"(c[3])
        : "r"(a[0]), "r"(a[1]), "r"(a[2]), "r"(a[3]), "r"(b0), "r"(b1));
}

__device__ __forceinline__ void atomicMaxFloat(float* addr, float val) {
    int* ai = (int*)addr;
    int old = __float_as_int(*addr);
    while (__int_as_float(old) < val) {
        int assumed = old;
        old = atomicCAS(ai, assumed, __float_as_int(val));
        if (old == assumed) break;
    }
}

// ---------------- dtype detection + index normalization ----------------
__global__ void detect_dtype(const unsigned long long* __restrict__ ei) {
    if (threadIdx.x == 0 && blockIdx.x == 0) {
        int is64 = 1;
        for (int i = 0; i < 64; i++)
            if (ei[i] >= (unsigned long long)NN) { is64 = 0; break; }
        g_is64 = is64;
    }
}
__global__ void cvt_edges(const void* __restrict__ ei) {
    int e = blockIdx.x * blockDim.x + threadIdx.x;
    if (e >= NE) return;
    if (g_is64) {
        const long long* p = (const long long*)ei;
        g_src[e] = (int)p[e];
        g_dst[e] = (int)p[NE + e];
    } else {
        const int* p = (const int*)ei;
        g_src[e] = p[e];
        g_dst[e] = p[NE + e];
    }
}
__global__ void cvt_batch(const void* __restrict__ b) {
    int n = blockIdx.x * blockDim.x + threadIdx.x;
    if (n >= NN) return;
    if (g_is64) g_batch[n] = (int)((const long long*)b)[n];
    else        g_batch[n] = ((const int*)b)[n];
}

// ---------------- zero / init kernels ----------------
__global__ void zero_m() {
    size_t i = (size_t)blockIdx.x * blockDim.x + threadIdx.x;
    if (i < (size_t)NN * 64) ((float4*)g_m)[i] = make_float4(0.f, 0.f, 0.f, 0.f);
}
__global__ void zero_deg() {
    int i = blockIdx.x * blockDim.x + threadIdx.x;
    if (i < NN) g_deg[i] = 0.f;
}
__global__ void zero_stats() {
    int c = threadIdx.x;
    g_sum[c] = 0.0; g_sumsq[c] = 0.0;
}
__global__ void init_pool() {
    int i = blockIdx.x * blockDim.x + threadIdx.x;
    if (i < NG * HID) g_pooled[i] = 0.f;
    if (i < NG) { g_smax[i] = -3.4e38f; g_denom[i] = 0.f; }
}
__global__ void init_s(const float* __restrict__ ba2) {
    int n = blockIdx.x * blockDim.x + threadIdx.x;
    if (n < NN) g_s[n] = ba2[0];
}

// ---------------- degree ----------------
__global__ void deg_kernel() {
    int e = blockIdx.x * blockDim.x + threadIdx.x;
    if (e < NE) atomicAdd(&g_deg[g_dst[e]], 1.f);
}
__global__ void inv_kernel() {
    int n = blockIdx.x * blockDim.x + threadIdx.x;
    if (n < NN) g_inv[n] = 1.f / fmaxf(g_deg[n], 1.f);
}

// ---------------- split A (f32 -> bf16 hi/lo, zero-padded to KP) ----------------
__global__ void split_a(const float* __restrict__ xext, int use_h, int K, int KP) {
    const float* __restrict__ A = use_h ? g_h : xext;
    int kp2 = KP >> 1;
    int i = blockIdx.x * blockDim.x + threadIdx.x;
    if (i >= NN * kp2) return;
    int n = i / kp2, k2 = (i - n * kp2) * 2;
    float v0 = (k2 < K)     ? A[(size_t)n * K + k2]     : 0.f;
    float v1 = (k2 + 1 < K) ? A[(size_t)n * K + k2 + 1] : 0.f;
    __nv_bfloat16 h0 = __float2bfloat16(v0), h1 = __float2bfloat16(v1);
    __nv_bfloat16 l0 = __float2bfloat16(v0 - __bfloat162float(h0));
    __nv_bfloat16 l1 = __float2bfloat16(v1 - __bfloat162float(h1));
    __nv_bfloat162 hp; hp.x = h0; hp.y = h1;
    __nv_bfloat162 lp; lp.x = l0; lp.y = l1;
    *(__nv_bfloat162*)(g_ah + (size_t)n * KP + k2) = hp;
    *(__nv_bfloat162*)(g_al + (size_t)n * KP + k2) = lp;
}

// ---------------- pack [Wl|Wr]^T into [512 rows x KP] bf16 hi/lo ----------------
__global__ void pack_wbT(const float* __restrict__ Wl, const float* __restrict__ Wr,
                         int K, int KP) {
    int kp2 = KP >> 1;
    int i = blockIdx.x * blockDim.x + threadIdx.x;
    if (i >= 512 * kp2) return;
    int n = i / kp2, k2 = (i - n * kp2) * 2;
    const float* W = (n < 256) ? Wl : Wr;
    int c = (n < 256) ? n : n - 256;
    float v0 = (k2 < K)     ? W[(size_t)k2 * 256 + c]       : 0.f;
    float v1 = (k2 + 1 < K) ? W[(size_t)(k2 + 1) * 256 + c] : 0.f;
    __nv_bfloat16 h0 = __float2bfloat16(v0), h1 = __float2bfloat16(v1);
    __nv_bfloat16 l0 = __float2bfloat16(v0 - __bfloat162float(h0));
    __nv_bfloat16 l1 = __float2bfloat16(v1 - __bfloat162float(h1));
    __nv_bfloat162 hp; hp.x = h0; hp.y = h1;
    __nv_bfloat162 lp; lp.x = l0; lp.y = l1;
    *(__nv_bfloat162*)(g_bh + (size_t)n * KP + k2) = hp;
    *(__nv_bfloat162*)(g_bl + (size_t)n * KP + k2) = lp;
}

// ---------------- split-bf16 GEMM via mma.sync (HMMA, baseline PTX) ----------------
// CTA: 128 threads = 2x2 warps. Tile M128 x N64, K chunks of 32.
// acc += Ah*Bh + Al*Bh + Ah*Bl (fp32 accum); grid.x = n-blocks (A reuse via L2).
__global__ __launch_bounds__(128) void gemm_tc(int KP) {
    __shared__ __align__(128) char sm_[24576];
    const uint32_t sb = smem_u32(sm_);   // A_hi 0 | A_lo 8192 | B_hi 16384 | B_lo 20480
    int tid = threadIdx.x, lane = tid & 31, wid = tid >> 5;
    int wm = wid >> 1, wn = wid & 1;
    int row0 = blockIdx.y * 128;
    int col0 = blockIdx.x * 64;
    int nch = KP >> 5;

    float acc[4][4][4];
#pragma unroll
    for (int a = 0; a < 4; a++)
#pragma unroll
        for (int b = 0; b < 4; b++)
#pragma unroll
            for (int c = 0; c < 4; c++) acc[a][b][c] = 0.f;

    for (int ch = 0; ch < nch; ch++) {
        __syncthreads();
        // stage A hi/lo: 2 x (128 rows x 64B) = 1024 16B-segments
#pragma unroll
        for (int i = 0; i < 8; i++) {
            int idx = i * 128 + tid;
            int half = idx >> 9, seg = idx & 511;
            int r = seg >> 2, s = (seg & 3) * 16;
            int gr = row0 + r;
            float4 v = make_float4(0.f, 0.f, 0.f, 0.f);
            if (gr < NN) {
                const char* base = (const char*)(half ? g_al : g_ah);
                v = *(const float4*)(base + ((size_t)gr * KP + ch * 32) * 2 + s);
            }
            uint32_t b = (uint32_t)(r * 64 + s);
            sts128(sb + half * 8192 + SWZ(b), v);
        }
        // stage B hi/lo: 2 x (64 rows x 64B) = 512 segments
#pragma unroll
        for (int i = 0; i < 4; i++) {
            int idx = i * 128 + tid;
            int half = idx >> 8, seg = idx & 255;
            int r = seg >> 2, s = (seg & 3) * 16;
            int gn = col0 + r;
            const char* base = (const char*)(half ? g_bl : g_bh);
            float4 v = *(const float4*)(base + ((size_t)gn * KP + ch * 32) * 2 + s);
            uint32_t b = (uint32_t)(r * 64 + s);
            sts128(sb + 16384 + half * 4096 + SWZ(b), v);
        }
        __syncthreads();

        int q = lane >> 3, lr = lane & 7;
#pragma unroll
        for (int ks = 0; ks < 2; ks++) {
            uint32_t Ah[4][4], Al[4][4], Bh[2][4], Bl[2][4];
#pragma unroll
            for (int mi = 0; mi < 4; mi++) {
                int row = wm * 64 + mi * 16 + (q & 1) * 8 + lr;
                uint32_t b = (uint32_t)(row * 64 + ks * 32 + (q >> 1) * 16);
                uint32_t a = sb + SWZ(b);
                ldsm4(Ah[mi], a);
                ldsm4(Al[mi], a + 8192);
            }
#pragma unroll
            for (int p = 0; p < 2; p++) {
                int nrow = wn * 32 + p * 16 + (q >> 1) * 8 + lr;
                uint32_t b = (uint32_t)(nrow * 64 + ks * 32 + (q & 1) * 16);
                uint32_t a = sb + 16384 + SWZ(b);
                ldsm4(Bh[p], a);
                ldsm4(Bl[p], a + 4096);
            }
#pragma unroll
            for (int mi = 0; mi < 4; mi++)
#pragma unroll
                for (int ni = 0; ni < 4; ni++) {
                    uint32_t bh0 = Bh[ni >> 1][(ni & 1) * 2], bh1 = Bh[ni >> 1][(ni & 1) * 2 + 1];
                    uint32_t bl0 = Bl[ni >> 1][(ni & 1) * 2], bl1 = Bl[ni >> 1][(ni & 1) * 2 + 1];
                    mma_bf16(acc[mi][ni], Ah[mi], bh0, bh1);
                    mma_bf16(acc[mi][ni], Al[mi], bh0, bh1);
                    mma_bf16(acc[mi][ni], Ah[mi], bl0, bl1);
                }
        }
    }

    // epilogue: direct register -> global
    int tr = lane >> 2, tc = lane & 3;
#pragma unroll
    for (int mi = 0; mi < 4; mi++)
#pragma unroll
        for (int half = 0; half < 2; half++) {
            int row = row0 + wm * 64 + mi * 16 + tr + half * 8;
            if (row < NN) {
                float* p = g_ylr + (size_t)row * 512 + col0 + wn * 32 + tc * 2;
#pragma unroll
                for (int ni = 0; ni < 4; ni++) {
                    float2 v = make_float2(acc[mi][ni][half * 2], acc[mi][ni][half * 2 + 1]);
                    *(float2*)(p + ni * 8) = v;
                }
            }
        }
}

// ---------------- edge scatter: g_m[dst] += yl part of g_ylr[src] ----------------
__global__ void scatter_kernel() {
    int e = blockIdx.x * 4 + (threadIdx.x >> 6);
    if (e >= NE) return;
    int c   = (threadIdx.x & 63) * 4;
    int src = g_src[e];
    int dst = g_dst[e];
    float4 v = *(const float4*)(g_ylr + (size_t)src * 512 + c);
    float* mp = g_m + (size_t)dst * 256 + c;
    atomicAdd(mp + 0, v.x);
    atomicAdd(mp + 1, v.y);
    atomicAdd(mp + 2, v.z);
    atomicAdd(mp + 3, v.w);
}

// ---------------- combine + BN stats ----------------
__global__ void combine_stats(const float* __restrict__ bl) {
    int c  = threadIdx.x;
    int r0 = blockIdx.x * 256;
    int r1 = min(r0 + 256, NN);
    float bias = bl[c];
    float s = 0.f, s2 = 0.f;
    for (int r = r0; r < r1; r++) {
        float pre = g_m[(size_t)r * 256 + c] * g_inv[r] + bias + g_ylr[(size_t)r * 512 + 256 + c];
        g_m[(size_t)r * 256 + c] = pre;
        s += pre; s2 += pre * pre;
    }
    atomicAdd(&g_sum[c], (double)s);
    atomicAdd(&g_sumsq[c], (double)s2);
}

__global__ void finalize_bn(const float* __restrict__ gm, const float* __restrict__ bt) {
    int c = threadIdx.x;
    double mean = g_sum[c] / (double)NN;
    double var  = g_sumsq[c] / (double)NN - mean * mean;
    float rstd  = rsqrtf((float)var + 1e-5f);
    float sc    = rstd * gm[c];
    g_scale[c]  = sc;
    g_shift[c]  = bt[c] - (float)mean * sc;
}

__global__ void bnrelu() {
    size_t i = (size_t)blockIdx.x * blockDim.x + threadIdx.x;
    if (i >= (size_t)NN * 64) return;
    size_t idx = i * 4;
    int c = (int)(idx & 255);
    float4 v = *(const float4*)(g_m + idx);
    v.x = fmaxf(v.x * g_scale[c + 0] + g_shift[c + 0], 0.f);
    v.y = fmaxf(v.y * g_scale[c + 1] + g_shift[c + 1], 0.f);
    v.z = fmaxf(v.z * g_scale[c + 2] + g_shift[c + 2], 0.f);
    v.w = fmaxf(v.w * g_scale[c + 3] + g_shift[c + 3], 0.f);
    *(float4*)(g_h + idx) = v;
}

// ---------------- attention score (j-split, static 40KB smem) ----------------
__global__ __launch_bounds__(256) void score_kernel(const float* __restrict__ Wa1,
                                                    const float* __restrict__ ba1,
                                                    const float* __restrict__ Wa2) {
    __shared__ float Wa1s[256 * 32];
    __shared__ float hrow[8 * 256];
    int jblk = blockIdx.x;
    int tid  = threadIdx.x;
    for (int i = tid; i < 256 * 32; i += 256) {
        int k = i >> 5, jj = i & 31;
        Wa1s[i] = Wa1[k * 128 + jblk * 32 + jj];
    }
    int jj = tid & 31, nd = tid >> 5;
    int j  = jblk * 32 + jj;
    float b1 = ba1[j], w2 = Wa2[j];
    __syncthreads();
    for (int n0 = blockIdx.y * 8; n0 < NN; n0 += gridDim.y * 8) {
        __syncthreads();
        for (int i = tid; i < 512; i += 256) {
            int r = n0 + (i >> 6);
            float4 v = (r < NN) ? *(const float4*)(g_h + (size_t)r * 256 + (size_t)(i & 63) * 4)
                                : make_float4(0.f, 0.f, 0.f, 0.f);
            *(float4*)&hrow[i * 4] = v;
        }
        __syncthreads();
        int n = n0 + nd;
        float acc = b1;
        const float* hp = hrow + nd * 256;
#pragma unroll 8
        for (int k = 0; k < 256; k++) acc += hp[k] * Wa1s[k * 32 + jj];
        float t = tanhf(acc) * w2;
#pragma unroll
        for (int o = 16; o; o >>= 1) t += __shfl_down_sync(0xffffffffu, t, o);
        if (jj == 0 && n < NN) atomicAdd(&g_s[n], t);
    }
}

// ---------------- per-graph softmax ----------------
__global__ void segmax_kernel() {
    int n  = blockIdx.x * blockDim.x + threadIdx.x;
    int nc = min(n, NN - 1);
    int g  = g_batch[nc];
    float v = (n < NN) ? g_s[n] : -3.4e38f;
    int g0 = __shfl_sync(0xffffffffu, g, 0);
    bool uni = __all_sync(0xffffffffu, g == g0);
    if (uni) {
#pragma unroll
        for (int o = 16; o; o >>= 1) v = fmaxf(v, __shfl_down_sync(0xffffffffu, v, o));
        if ((threadIdx.x & 31) == 0) atomicMaxFloat(&g_smax[g0], v);
    } else if (n < NN) {
        atomicMaxFloat(&g_smax[g], v);
    }
}

__global__ void expsum_kernel() {
    int n  = blockIdx.x * blockDim.x + threadIdx.x;
    int nc = min(n, NN - 1);
    int g  = g_batch[nc];
    float e = 0.f;
    if (n < NN) { e = expf(g_s[n] - g_smax[g]); g_w[n] = e; }
    int g0 = __shfl_sync(0xffffffffu, g, 0);
    bool uni = __all_sync(0xffffffffu, g == g0);
    if (uni) {
#pragma unroll
        for (int o = 16; o; o >>= 1) e += __shfl_down_sync(0xffffffffu, e, o);
        if ((threadIdx.x & 31) == 0) atomicAdd(&g_denom[g0], e);
    } else if (n < NN) {
        atomicAdd(&g_denom[g], e);
    }
}

__global__ void weights_kernel() {
    int n = blockIdx.x * blockDim.x + threadIdx.x;
    if (n < NN) g_w[n] = g_w[n] / g_denom[g_batch[n]];
}

// ---------------- weighted pooling (sorted batch -> running flush) ----------------
__global__ void pooled_kernel() {
    int c  = threadIdx.x;
    int r0 = blockIdx.x * 512;
    if (r0 >= NN) return;
    int r1  = min(r0 + 512, NN);
    int cur = g_batch[r0];
    float acc = 0.f;
    for (int r = r0; r < r1; r++) {
        int g = g_batch[r];
        if (g != cur) { atomicAdd(&g_pooled[cur * 256 + c], acc); acc = 0.f; cur = g; }
        acc += g_h[(size_t)r * 256 + c] * g_w[r];
    }
    atomicAdd(&g_pooled[cur * 256 + c], acc);
}

// ---------------- classifier ----------------
__global__ void classifier_kernel(const float* __restrict__ Wc1, const float* __restrict__ bc1,
                                  const float* __restrict__ Wc2, const float* __restrict__ bc2,
                                  float* __restrict__ out) {
    int g = blockIdx.x;
    int j = threadIdx.x;
    float acc = bc1[j];
    for (int k = 0; k < 256; k++) acc += g_pooled[g * 256 + k] * Wc1[k * 128 + j];
    float t = fmaxf(acc, 0.f) * Wc2[j];
#pragma unroll
    for (int o = 16; o; o >>= 1) t += __shfl_down_sync(0xffffffffu, t, o);
    __shared__ float red[4];
    if ((j & 31) == 0) red[j >> 5] = t;
    __syncthreads();
    if (j == 0) out[g] = red[0] + red[1] + red[2] + red[3] + bc2[0];
}

// ---------------- launch ----------------
extern "C" void kernel_launch(void* const* d_in, const int* in_sizes, int n_in,
                              void* d_out, int out_size) {
    const float* x     = (const float*)d_in[0];
    const void*  ei    = d_in[1];
    const void*  batch = d_in[2];
    const float* Wl[3] = {(const float*)d_in[3], (const float*)d_in[8],  (const float*)d_in[13]};
    const float* bl[3] = {(const float*)d_in[4], (const float*)d_in[9],  (const float*)d_in[14]};
    const float* Wr[3] = {(const float*)d_in[5], (const float*)d_in[10], (const float*)d_in[15]};
    const float* gg[3] = {(const float*)d_in[6], (const float*)d_in[11], (const float*)d_in[16]};
    const float* bb[3] = {(const float*)d_in[7], (const float*)d_in[12], (const float*)d_in[17]};
    const float* Wa1 = (const float*)d_in[18];
    const float* ba1 = (const float*)d_in[19];
    const float* Wa2 = (const float*)d_in[20];
    const float* ba2 = (const float*)d_in[21];
    const float* Wc1 = (const float*)d_in[22];
    const float* bc1 = (const float*)d_in[23];
    const float* Wc2 = (const float*)d_in[24];
    const float* bc2 = (const float*)d_in[25];
    float* out = (float*)d_out;

    detect_dtype<<<1, 32>>>((const unsigned long long*)ei);
    cvt_edges<<<(NE + 255) / 256, 256>>>(ei);
    cvt_batch<<<(NN + 255) / 256, 256>>>(batch);

    zero_deg<<<(NN + 255) / 256, 256>>>();
    deg_kernel<<<(NE + 255) / 256, 256>>>();
    inv_kernel<<<(NN + 255) / 256, 256>>>();

    for (int L = 0; L < 3; L++) {
        int K  = (L == 0) ? IND : HID;
        int KP = (L == 0) ? KP0 : HID;
        split_a<<<(NN * (KP / 2) + 255) / 256, 256>>>(x, L ? 1 : 0, K, KP);
        pack_wbT<<<(512 * (KP / 2) + 255) / 256, 256>>>(Wl[L], Wr[L], K, KP);
        dim3 ggrid(8, (NN + 127) / 128);   // x = n-blocks (share A rows via L2)
        gemm_tc<<<ggrid, 128>>>(KP);
        zero_m<<<(NN * 64 + 255) / 256, 256>>>();
        scatter_kernel<<<(NE + 3) / 4, 256>>>();
        zero_stats<<<1, 256>>>();
        combine_stats<<<(NN + 255) / 256, 256>>>(bl[L]);
        finalize_bn<<<1, 256>>>(gg[L], bb[L]);
        bnrelu<<<(NN * 64 + 255) / 256, 256>>>();
    }

    init_s<<<(NN + 255) / 256, 256>>>(ba2);
    {
        dim3 sgrid(4, 592);
        score_kernel<<<sgrid, 256>>>(Wa1, ba1, Wa2);
    }
    init_pool<<<(NG * HID + 255) / 256, 256>>>();
    segmax_kernel<<<(NN + 255) / 256, 256>>>();
    expsum_kernel<<<(NN + 255) / 256, 256>>>();
    weights_kernel<<<(NN + 255) / 256, 256>>>();
    pooled_kernel<<<(NN + 511) / 512, 256>>>();
    classifier_kernel<<<NG, 128>>>(Wc1, bc1, Wc2, bc2, out);
}

// round 6
// speedup vs baseline: 2.0783x; 1.2599x over previous
#include <cuda_runtime.h>
#include <cuda_bf16.h>
#include <math.h>
#include <stdint.h>

#define NN 100000
#define NE 400000
#define IND 771
#define HID 256
#define NG 64
#define KP0 800            // padded K for layer 0 (25 chunks of 32)
#define NBLK 391           // ceil(NN/256)

// ---------------- scratch (static device globals; no allocation) ----------------
__device__ float  g_ylr[(size_t)NN * 512];   // [yl | yr] per node
__device__ float  g_m[(size_t)NN * 256];     // pre-BN
__device__ float  g_h[(size_t)NN * 256];     // final layer output
__device__ float  g_inv[NN];
__device__ double g_sum[256];
__device__ double g_sumsq[256];
__device__ float  g_scale[256];
__device__ float  g_shift[256];
__device__ float  g_s[NN];
__device__ float  g_w[NN];
__device__ float  g_smax[NG];
__device__ float  g_denom[NG];
__device__ float  g_pooled[NG * HID];
__device__ int    g_is64;
__device__ int    g_src[NE];
__device__ int    g_dst[NE];
__device__ int    g_batch[NN];
// CSR by dst (built once, reused all 3 layers)
__device__ int    g_cnt[NN];
__device__ int    g_off[NN];
__device__ int    g_cur[NN];
__device__ int    g_csr[NE];
__device__ int    g_bsum[NBLK];
__device__ int    g_boff[NBLK];
// bf16 split operands for tensor-core GEMM
__device__ __nv_bfloat16 g_ah[(size_t)NN * KP0];
__device__ __nv_bfloat16 g_al[(size_t)NN * KP0];
__device__ __nv_bfloat16 g_bh[512 * KP0];
__device__ __nv_bfloat16 g_bl[512 * KP0];

// ---------------- helpers ----------------
__device__ __forceinline__ uint32_t smem_u32(const void* p) {
    uint32_t a;
    asm("{ .reg .u64 t; cvta.to.shared.u64 t, %1; cvt.u32.u64 %0, t; }" : "=r"(a) : "l"(p));
    return a;
}
#define SWZ(b) ((b) ^ ((((b) >> 7) & 3) << 4))

__device__ __forceinline__ void sts128(uint32_t addr, float4 v) {
    asm volatile("st.shared.v4.b32 [%0], {%1,%2,%3,%4};"
                 :: "r"(addr), "r"(__float_as_uint(v.x)), "r"(__float_as_uint(v.y)),
                    "r"(__float_as_uint(v.z)), "r"(__float_as_uint(v.w)) : "memory");
}
__device__ __forceinline__ void ldsm4(uint32_t* r, uint32_t addr) {
    asm volatile("ldmatrix.sync.aligned.m8n8.x4.shared.b16 {%0,%1,%2,%3}, [%4];"
                 : "=r"(r[0]), "=r"(r[1]), "=r"(r[2]), "=r"(r[3]) : "r"(addr));
}
__device__ __forceinline__ void mma_bf16(float* c, const uint32_t* a, uint32_t b0, uint32_t b1) {
    asm volatile(
        "mma.sync.aligned.m16n8k16.row.col.f32.bf16.bf16.f32 "
        "{%0,%1,%2,%3}, {%4,%5,%6,%7}, {%8,%9}, {%0,%1,%2,%3};"
        : "+f"(c[0]), "+f"(c[1]), "+f"(c[2]), "+f"(c[3])
        : "r"(a[0]), "r"(a[1]), "r"(a[2]), "r"(a[3]), "r"(b0), "r"(b1));
}
__device__ __forceinline__ void atomicMaxFloat(float* addr, float val) {
    int* ai = (int*)addr;
    int old = __float_as_int(*addr);
    while (__int_as_float(old) < val) {
        int assumed = old;
        old = atomicCAS(ai, assumed, __float_as_int(val));
        if (old == assumed) break;
    }
}
__device__ __forceinline__ void split1(float v, __nv_bfloat16& h, __nv_bfloat16& l) {
    h = __float2bfloat16(v);
    l = __float2bfloat16(v - __bfloat162float(h));
}

// ---------------- dtype detection + index normalization ----------------
__global__ void detect_dtype(const unsigned long long* __restrict__ ei) {
    if (threadIdx.x == 0 && blockIdx.x == 0) {
        int is64 = 1;
        for (int i = 0; i < 64; i++)
            if (ei[i] >= (unsigned long long)NN) { is64 = 0; break; }
        g_is64 = is64;
    }
}
__global__ void cvt_edges(const void* __restrict__ ei) {
    int e = blockIdx.x * blockDim.x + threadIdx.x;
    if (e >= NE) return;
    if (g_is64) {
        const long long* p = (const long long*)ei;
        g_src[e] = (int)p[e];
        g_dst[e] = (int)p[NE + e];
    } else {
        const int* p = (const int*)ei;
        g_src[e] = p[e];
        g_dst[e] = p[NE + e];
    }
}
__global__ void cvt_batch_zero(const void* __restrict__ b) {
    int n = blockIdx.x * blockDim.x + threadIdx.x;
    if (n >= NN) return;
    if (g_is64) g_batch[n] = (int)((const long long*)b)[n];
    else        g_batch[n] = ((const int*)b)[n];
    g_cnt[n] = 0;
}

// ---------------- CSR build ----------------
__global__ void cnt_kernel() {
    int e = blockIdx.x * blockDim.x + threadIdx.x;
    if (e < NE) atomicAdd(&g_cnt[g_dst[e]], 1);
}
__global__ void scan1() {
    __shared__ int sm[256];
    int b = blockIdx.x, t = threadIdx.x;
    int i = b * 256 + t;
    int v = (i < NN) ? g_cnt[i] : 0;
    sm[t] = v; __syncthreads();
    for (int o = 1; o < 256; o <<= 1) {
        int u = (t >= o) ? sm[t - o] : 0;
        __syncthreads();
        sm[t] += u;
        __syncthreads();
    }
    if (i < NN) g_off[i] = sm[t] - v;
    if (t == 255) g_bsum[b] = sm[255];
}
__global__ void scan2() {
    __shared__ int sm[512];
    int t = threadIdx.x;
    int v = (t < NBLK) ? g_bsum[t] : 0;
    sm[t] = v; __syncthreads();
    for (int o = 1; o < 512; o <<= 1) {
        int u = (t >= o) ? sm[t - o] : 0;
        __syncthreads();
        sm[t] += u;
        __syncthreads();
    }
    if (t < NBLK) g_boff[t] = sm[t] - v;
}
__global__ void scan3() {
    int i = blockIdx.x * blockDim.x + threadIdx.x;
    if (i < NN) {
        int o = g_off[i] + g_boff[i >> 8];
        g_off[i] = o;
        g_cur[i] = o;
        g_inv[i] = 1.f / fmaxf((float)g_cnt[i], 1.f);
    }
}
__global__ void place_kernel() {
    int e = blockIdx.x * blockDim.x + threadIdx.x;
    if (e < NE) {
        int pos = atomicAdd(&g_cur[g_dst[e]], 1);
        g_csr[pos] = g_src[e];
    }
}

// ---------------- zero / init ----------------
__global__ void zero_stats() {
    int c = threadIdx.x;
    g_sum[c] = 0.0; g_sumsq[c] = 0.0;
}
__global__ void init_pool() {
    int i = blockIdx.x * blockDim.x + threadIdx.x;
    if (i < NG * HID) g_pooled[i] = 0.f;
    if (i < NG) { g_smax[i] = -3.4e38f; g_denom[i] = 0.f; }
}
__global__ void init_s(const float* __restrict__ ba2) {
    int n = blockIdx.x * blockDim.x + threadIdx.x;
    if (n < NN) g_s[n] = ba2[0];
}

// ---------------- split x (f32 -> bf16 hi/lo, zero-padded to KP0), layer 0 only ----------------
__global__ void split_a(const float* __restrict__ A) {
    int kp2 = KP0 >> 1;
    int i = blockIdx.x * blockDim.x + threadIdx.x;
    if (i >= NN * kp2) return;
    int n = i / kp2, k2 = (i - n * kp2) * 2;
    float v0 = (k2 < IND)     ? A[(size_t)n * IND + k2]     : 0.f;
    float v1 = (k2 + 1 < IND) ? A[(size_t)n * IND + k2 + 1] : 0.f;
    __nv_bfloat162 hp, lp;
    split1(v0, hp.x, lp.x);
    split1(v1, hp.y, lp.y);
    *(__nv_bfloat162*)(g_ah + (size_t)n * KP0 + k2) = hp;
    *(__nv_bfloat162*)(g_al + (size_t)n * KP0 + k2) = lp;
}

// ---------------- pack [Wl|Wr]^T into [512 rows x KP] bf16 hi/lo ----------------
__global__ void pack_wbT(const float* __restrict__ Wl, const float* __restrict__ Wr,
                         int K, int KP) {
    int kp2 = KP >> 1;
    int i = blockIdx.x * blockDim.x + threadIdx.x;
    if (i >= 512 * kp2) return;
    int n = i / kp2, k2 = (i - n * kp2) * 2;
    const float* W = (n < 256) ? Wl : Wr;
    int c = (n < 256) ? n : n - 256;
    float v0 = (k2 < K)     ? W[(size_t)k2 * 256 + c]       : 0.f;
    float v1 = (k2 + 1 < K) ? W[(size_t)(k2 + 1) * 256 + c] : 0.f;
    __nv_bfloat162 hp, lp;
    split1(v0, hp.x, lp.x);
    split1(v1, hp.y, lp.y);
    *(__nv_bfloat162*)(g_bh + (size_t)n * KP + k2) = hp;
    *(__nv_bfloat162*)(g_bl + (size_t)n * KP + k2) = lp;
}

// ---------------- split-bf16 GEMM via mma.sync ----------------
__global__ __launch_bounds__(128) void gemm_tc(int KP) {
    __shared__ __align__(128) char sm_[24576];
    const uint32_t sb = smem_u32(sm_);   // A_hi 0 | A_lo 8192 | B_hi 16384 | B_lo 20480
    int tid = threadIdx.x, lane = tid & 31, wid = tid >> 5;
    int wm = wid >> 1, wn = wid & 1;
    int row0 = blockIdx.y * 128;
    int col0 = blockIdx.x * 64;
    int nch = KP >> 5;

    float acc[4][4][4];
#pragma unroll
    for (int a = 0; a < 4; a++)
#pragma unroll
        for (int b = 0; b < 4; b++)
#pragma unroll
            for (int c = 0; c < 4; c++) acc[a][b][c] = 0.f;

    for (int ch = 0; ch < nch; ch++) {
        __syncthreads();
#pragma unroll
        for (int i = 0; i < 8; i++) {
            int idx = i * 128 + tid;
            int half = idx >> 9, seg = idx & 511;
            int r = seg >> 2, s = (seg & 3) * 16;
            int gr = row0 + r;
            float4 v = make_float4(0.f, 0.f, 0.f, 0.f);
            if (gr < NN) {
                const char* base = (const char*)(half ? g_al : g_ah);
                v = *(const float4*)(base + ((size_t)gr * KP + ch * 32) * 2 + s);
            }
            uint32_t b = (uint32_t)(r * 64 + s);
            sts128(sb + half * 8192 + SWZ(b), v);
        }
#pragma unroll
        for (int i = 0; i < 4; i++) {
            int idx = i * 128 + tid;
            int half = idx >> 8, seg = idx & 255;
            int r = seg >> 2, s = (seg & 3) * 16;
            int gn = col0 + r;
            const char* base = (const char*)(half ? g_bl : g_bh);
            float4 v = *(const float4*)(base + ((size_t)gn * KP + ch * 32) * 2 + s);
            uint32_t b = (uint32_t)(r * 64 + s);
            sts128(sb + 16384 + half * 4096 + SWZ(b), v);
        }
        __syncthreads();

        int q = lane >> 3, lr = lane & 7;
#pragma unroll
        for (int ks = 0; ks < 2; ks++) {
            uint32_t Ah[4][4], Al[4][4], Bh[2][4], Bl[2][4];
#pragma unroll
            for (int mi = 0; mi < 4; mi++) {
                int row = wm * 64 + mi * 16 + (q & 1) * 8 + lr;
                uint32_t b = (uint32_t)(row * 64 + ks * 32 + (q >> 1) * 16);
                uint32_t a = sb + SWZ(b);
                ldsm4(Ah[mi], a);
                ldsm4(Al[mi], a + 8192);
            }
#pragma unroll
            for (int p = 0; p < 2; p++) {
                int nrow = wn * 32 + p * 16 + (q >> 1) * 8 + lr;
                uint32_t b = (uint32_t)(nrow * 64 + ks * 32 + (q & 1) * 16);
                uint32_t a = sb + 16384 + SWZ(b);
                ldsm4(Bh[p], a);
                ldsm4(Bl[p], a + 4096);
            }
#pragma unroll
            for (int mi = 0; mi < 4; mi++)
#pragma unroll
                for (int ni = 0; ni < 4; ni++) {
                    uint32_t bh0 = Bh[ni >> 1][(ni & 1) * 2], bh1 = Bh[ni >> 1][(ni & 1) * 2 + 1];
                    uint32_t bl0 = Bl[ni >> 1][(ni & 1) * 2], bl1 = Bl[ni >> 1][(ni & 1) * 2 + 1];
                    mma_bf16(acc[mi][ni], Ah[mi], bh0, bh1);
                    mma_bf16(acc[mi][ni], Al[mi], bh0, bh1);
                    mma_bf16(acc[mi][ni], Ah[mi], bl0, bl1);
                }
        }
    }

    int tr = lane >> 2, tc = lane & 3;
#pragma unroll
    for (int mi = 0; mi < 4; mi++)
#pragma unroll
        for (int half = 0; half < 2; half++) {
            int row = row0 + wm * 64 + mi * 16 + tr + half * 8;
            if (row < NN) {
                float* p = g_ylr + (size_t)row * 512 + col0 + wn * 32 + tc * 2;
#pragma unroll
                for (int ni = 0; ni < 4; ni++) {
                    float2 v = make_float2(acc[mi][ni][half * 2], acc[mi][ni][half * 2 + 1]);
                    *(float2*)(p + ni * 8) = v;
                }
            }
        }
}

// ---------------- CSR aggregation + combine + BN stats (no atomics on features) ----------------
// pre = (sum_{j in N(r)} yl[j]) * inv[r] + bl + yr[r];  writes g_m, accumulates stats.
__global__ __launch_bounds__(256) void agg_combine(const float* __restrict__ bl) {
    int c  = threadIdx.x;
    int r0 = blockIdx.x * 64;
    int r1 = min(r0 + 64, NN);
    float bias = bl[c];
    float s = 0.f, s2 = 0.f;
    for (int r = r0; r < r1; r++) {
        int beg = g_off[r];
        int end = (r == NN - 1) ? NE : g_off[r + 1];
        float acc = 0.f;
        for (int i = beg; i < end; i++) {
            int src = g_csr[i];
            acc += g_ylr[(size_t)src * 512 + c];
        }
        float pre = acc * g_inv[r] + bias + g_ylr[(size_t)r * 512 + 256 + c];
        g_m[(size_t)r * 256 + c] = pre;
        s += pre; s2 += pre * pre;
    }
    atomicAdd(&g_sum[c], (double)s);
    atomicAdd(&g_sumsq[c], (double)s2);
}

__global__ void finalize_bn(const float* __restrict__ gm, const float* __restrict__ bt) {
    int c = threadIdx.x;
    double mean = g_sum[c] / (double)NN;
    double var  = g_sumsq[c] / (double)NN - mean * mean;
    float rstd  = rsqrtf((float)var + 1e-5f);
    float sc    = rstd * gm[c];
    g_scale[c]  = sc;
    g_shift[c]  = bt[c] - (float)mean * sc;
}

// bnrelu: split==1 -> write bf16 hi/lo (next layer GEMM input, KP=256);
//         split==0 -> write fp32 g_h (final layer).
__global__ void bnrelu(int split) {
    size_t i = (size_t)blockIdx.x * blockDim.x + threadIdx.x;
    if (i >= (size_t)NN * 64) return;
    size_t idx = i * 4;
    int c = (int)(idx & 255);
    float4 v = *(const float4*)(g_m + idx);
    v.x = fmaxf(v.x * g_scale[c + 0] + g_shift[c + 0], 0.f);
    v.y = fmaxf(v.y * g_scale[c + 1] + g_shift[c + 1], 0.f);
    v.z = fmaxf(v.z * g_scale[c + 2] + g_shift[c + 2], 0.f);
    v.w = fmaxf(v.w * g_scale[c + 3] + g_shift[c + 3], 0.f);
    if (split) {
        __nv_bfloat162 h01, l01, h23, l23;
        split1(v.x, h01.x, l01.x);
        split1(v.y, h01.y, l01.y);
        split1(v.z, h23.x, l23.x);
        split1(v.w, h23.y, l23.y);
        uint2 uh, ul;
        uh.x = *(uint32_t*)&h01; uh.y = *(uint32_t*)&h23;
        ul.x = *(uint32_t*)&l01; ul.y = *(uint32_t*)&l23;
        *(uint2*)(g_ah + idx) = uh;
        *(uint2*)(g_al + idx) = ul;
    } else {
        *(float4*)(g_h + idx) = v;
    }
}

// ---------------- attention score (j-split, static 40KB smem) ----------------
__global__ __launch_bounds__(256) void score_kernel(const float* __restrict__ Wa1,
                                                    const float* __restrict__ ba1,
                                                    const float* __restrict__ Wa2) {
    __shared__ float Wa1s[256 * 32];
    __shared__ float hrow[8 * 256];
    int jblk = blockIdx.x;
    int tid  = threadIdx.x;
    for (int i = tid; i < 256 * 32; i += 256) {
        int k = i >> 5, jj = i & 31;
        Wa1s[i] = Wa1[k * 128 + jblk * 32 + jj];
    }
    int jj = tid & 31, nd = tid >> 5;
    int j  = jblk * 32 + jj;
    float b1 = ba1[j], w2 = Wa2[j];
    __syncthreads();
    for (int n0 = blockIdx.y * 8; n0 < NN; n0 += gridDim.y * 8) {
        __syncthreads();
        for (int i = tid; i < 512; i += 256) {
            int r = n0 + (i >> 6);
            float4 v = (r < NN) ? *(const float4*)(g_h + (size_t)r * 256 + (size_t)(i & 63) * 4)
                                : make_float4(0.f, 0.f, 0.f, 0.f);
            *(float4*)&hrow[i * 4] = v;
        }
        __syncthreads();
        int n = n0 + nd;
        float acc = b1;
        const float* hp = hrow + nd * 256;
#pragma unroll 8
        for (int k = 0; k < 256; k++) acc += hp[k] * Wa1s[k * 32 + jj];
        float t = tanhf(acc) * w2;
#pragma unroll
        for (int o = 16; o; o >>= 1) t += __shfl_down_sync(0xffffffffu, t, o);
        if (jj == 0 && n < NN) atomicAdd(&g_s[n], t);
    }
}

// ---------------- per-graph softmax ----------------
__global__ void segmax_kernel() {
    int n  = blockIdx.x * blockDim.x + threadIdx.x;
    int nc = min(n, NN - 1);
    int g  = g_batch[nc];
    float v = (n < NN) ? g_s[n] : -3.4e38f;
    int g0 = __shfl_sync(0xffffffffu, g, 0);
    bool uni = __all_sync(0xffffffffu, g == g0);
    if (uni) {
#pragma unroll
        for (int o = 16; o; o >>= 1) v = fmaxf(v, __shfl_down_sync(0xffffffffu, v, o));
        if ((threadIdx.x & 31) == 0) atomicMaxFloat(&g_smax[g0], v);
    } else if (n < NN) {
        atomicMaxFloat(&g_smax[g], v);
    }
}

__global__ void expsum_kernel() {
    int n  = blockIdx.x * blockDim.x + threadIdx.x;
    int nc = min(n, NN - 1);
    int g  = g_batch[nc];
    float e = 0.f;
    if (n < NN) { e = expf(g_s[n] - g_smax[g]); g_w[n] = e; }
    int g0 = __shfl_sync(0xffffffffu, g, 0);
    bool uni = __all_sync(0xffffffffu, g == g0);
    if (uni) {
#pragma unroll
        for (int o = 16; o; o >>= 1) e += __shfl_down_sync(0xffffffffu, e, o);
        if ((threadIdx.x & 31) == 0) atomicAdd(&g_denom[g0], e);
    } else if (n < NN) {
        atomicAdd(&g_denom[g], e);
    }
}

__global__ void weights_kernel() {
    int n = blockIdx.x * blockDim.x + threadIdx.x;
    if (n < NN) g_w[n] = g_w[n] / g_denom[g_batch[n]];
}

// ---------------- weighted pooling ----------------
__global__ void pooled_kernel() {
    int c  = threadIdx.x;
    int r0 = blockIdx.x * 512;
    if (r0 >= NN) return;
    int r1  = min(r0 + 512, NN);
    int cur = g_batch[r0];
    float acc = 0.f;
    for (int r = r0; r < r1; r++) {
        int g = g_batch[r];
        if (g != cur) { atomicAdd(&g_pooled[cur * 256 + c], acc); acc = 0.f; cur = g; }
        acc += g_h[(size_t)r * 256 + c] * g_w[r];
    }
    atomicAdd(&g_pooled[cur * 256 + c], acc);
}

// ---------------- classifier ----------------
__global__ void classifier_kernel(const float* __restrict__ Wc1, const float* __restrict__ bc1,
                                  const float* __restrict__ Wc2, const float* __restrict__ bc2,
                                  float* __restrict__ out) {
    int g = blockIdx.x;
    int j = threadIdx.x;
    float acc = bc1[j];
    for (int k = 0; k < 256; k++) acc += g_pooled[g * 256 + k] * Wc1[k * 128 + j];
    float t = fmaxf(acc, 0.f) * Wc2[j];
#pragma unroll
    for (int o = 16; o; o >>= 1) t += __shfl_down_sync(0xffffffffu, t, o);
    __shared__ float red[4];
    if ((j & 31) == 0) red[j >> 5] = t;
    __syncthreads();
    if (j == 0) out[g] = red[0] + red[1] + red[2] + red[3] + bc2[0];
}

// ---------------- launch ----------------
extern "C" void kernel_launch(void* const* d_in, const int* in_sizes, int n_in,
                              void* d_out, int out_size) {
    const float* x     = (const float*)d_in[0];
    const void*  ei    = d_in[1];
    const void*  batch = d_in[2];
    const float* Wl[3] = {(const float*)d_in[3], (const float*)d_in[8],  (const float*)d_in[13]};
    const float* bl[3] = {(const float*)d_in[4], (const float*)d_in[9],  (const float*)d_in[14]};
    const float* Wr[3] = {(const float*)d_in[5], (const float*)d_in[10], (const float*)d_in[15]};
    const float* gg[3] = {(const float*)d_in[6], (const float*)d_in[11], (const float*)d_in[16]};
    const float* bb[3] = {(const float*)d_in[7], (const float*)d_in[12], (const float*)d_in[17]};
    const float* Wa1 = (const float*)d_in[18];
    const float* ba1 = (const float*)d_in[19];
    const float* Wa2 = (const float*)d_in[20];
    const float* ba2 = (const float*)d_in[21];
    const float* Wc1 = (const float*)d_in[22];
    const float* bc1 = (const float*)d_in[23];
    const float* Wc2 = (const float*)d_in[24];
    const float* bc2 = (const float*)d_in[25];
    float* out = (float*)d_out;

    // launches 1-4: layer-0 GEMM path first (4th launch = gemm_tc -> ncu capture slot)
    detect_dtype<<<1, 32>>>((const unsigned long long*)ei);
    split_a<<<(NN * (KP0 / 2) + 255) / 256, 256>>>(x);
    pack_wbT<<<(512 * (KP0 / 2) + 255) / 256, 256>>>(Wl[0], Wr[0], IND, KP0);
    {
        dim3 ggrid(8, (NN + 127) / 128);
        gemm_tc<<<ggrid, 128>>>(KP0);
    }

    // graph preprocessing (overlaps conceptually; sequential stream is fine)
    cvt_edges<<<(NE + 255) / 256, 256>>>(ei);
    cvt_batch_zero<<<(NN + 255) / 256, 256>>>(batch);
    cnt_kernel<<<(NE + 255) / 256, 256>>>();
    scan1<<<NBLK, 256>>>();
    scan2<<<1, 512>>>();
    scan3<<<(NN + 255) / 256, 256>>>();
    place_kernel<<<(NE + 255) / 256, 256>>>();

    for (int L = 0; L < 3; L++) {
        if (L > 0) {
            pack_wbT<<<(512 * (HID / 2) + 255) / 256, 256>>>(Wl[L], Wr[L], HID, HID);
            dim3 ggrid(8, (NN + 127) / 128);
            gemm_tc<<<ggrid, 128>>>(HID);
        }
        zero_stats<<<1, 256>>>();
        agg_combine<<<(NN + 63) / 64, 256>>>(bl[L]);
        finalize_bn<<<1, 256>>>(gg[L], bb[L]);
        bnrelu<<<(NN * 64 + 255) / 256, 256>>>(L < 2 ? 1 : 0);
    }

    init_s<<<(NN + 255) / 256, 256>>>(ba2);
    {
        dim3 sgrid(4, 592);
        score_kernel<<<sgrid, 256>>>(Wa1, ba1, Wa2);
    }
    init_pool<<<(NG * HID + 255) / 256, 256>>>();
    segmax_kernel<<<(NN + 255) / 256, 256>>>();
    expsum_kernel<<<(NN + 255) / 256, 256>>>();
    weights_kernel<<<(NN + 255) / 256, 256>>>();
    pooled_kernel<<<(NN + 511) / 512, 256>>>();
    classifier_kernel<<<NG, 128>>>(Wc1, bc1, Wc2, bc2, out);
}

// round 7
// speedup vs baseline: 2.4244x; 1.1665x over previous
#include <cuda_runtime.h>
#include <cuda_bf16.h>
#include <math.h>
#include <stdint.h>

#define NN 100000
#define NE 400000
#define IND 771
#define HID 256
#define NG 64
#define KP0 800            // padded K for layer 0 (25 chunks of 32)
#define NBLK 391           // ceil(NN/256)

// ---------------- scratch (static device globals; no allocation) ----------------
__device__ float  g_yl[(size_t)NN * 256];    // lin_l pre-agg (also score-GEMM scratch)
__device__ float  g_yr[(size_t)NN * 256];    // lin_r part
__device__ float  g_m[(size_t)NN * 256];     // pre-BN
__device__ float  g_h[(size_t)NN * 256];     // final layer output
__device__ float  g_inv[NN];
__device__ double g_sum[256];
__device__ double g_sumsq[256];
__device__ float  g_scale[256];
__device__ float  g_shift[256];
__device__ float  g_s[NN];
__device__ float  g_w[NN];
__device__ float  g_smax[NG];
__device__ float  g_denom[NG];
__device__ float  g_pooled[NG * HID];
__device__ int    g_is64;
__device__ int    g_src[NE];
__device__ int    g_dst[NE];
__device__ int    g_batch[NN];
// CSR by dst (built once, reused all 3 layers)
__device__ int    g_cnt[NN];
__device__ int    g_off[NN];
__device__ int    g_cur[NN];
__device__ int    g_csr[NE];
__device__ int    g_bsum[NBLK];
__device__ int    g_boff[NBLK];
// bf16 split operands for tensor-core GEMM
__device__ __nv_bfloat16 g_ah[(size_t)NN * KP0];
__device__ __nv_bfloat16 g_al[(size_t)NN * KP0];
__device__ __nv_bfloat16 g_bh[512 * KP0];
__device__ __nv_bfloat16 g_bl[512 * KP0];

// ---------------- helpers ----------------
__device__ __forceinline__ uint32_t smem_u32(const void* p) {
    uint32_t a;
    asm("{ .reg .u64 t; cvta.to.shared.u64 t, %1; cvt.u32.u64 %0, t; }" : "=r"(a) : "l"(p));
    return a;
}
#define SWZ(b) ((b) ^ ((((b) >> 7) & 3) << 4))

__device__ __forceinline__ void sts128(uint32_t addr, float4 v) {
    asm volatile("st.shared.v4.b32 [%0], {%1,%2,%3,%4};"
                 :: "r"(addr), "r"(__float_as_uint(v.x)), "r"(__float_as_uint(v.y)),
                    "r"(__float_as_uint(v.z)), "r"(__float_as_uint(v.w)) : "memory");
}
__device__ __forceinline__ void ldsm4(uint32_t* r, uint32_t addr) {
    asm volatile("ldmatrix.sync.aligned.m8n8.x4.shared.b16 {%0,%1,%2,%3}, [%4];"
                 : "=r"(r[0]), "=r"(r[1]), "=r"(r[2]), "=r"(r[3]) : "r"(addr));
}
__device__ __forceinline__ void mma_bf16(float* c, const uint32_t* a, uint32_t b0, uint32_t b1) {
    asm volatile(
        "mma.sync.aligned.m16n8k16.row.col.f32.bf16.bf16.f32 "
        "{%0,%1,%2,%3}, {%4,%5,%6,%7}, {%8,%9}, {%0,%1,%2,%3};"
        : "+f"(c[0]), "+f"(c[1]), "+f"(c[2]), "+f"(c[3])
        : "r"(a[0]), "r"(a[1]), "r"(a[2]), "r"(a[3]), "r"(b0), "r"(b1));
}
__device__ __forceinline__ void atomicMaxFloat(float* addr, float val) {
    int* ai = (int*)addr;
    int old = __float_as_int(*addr);
    while (__int_as_float(old) < val) {
        int assumed = old;
        old = atomicCAS(ai, assumed, __float_as_int(val));
        if (old == assumed) break;
    }
}
__device__ __forceinline__ void split1(float v, __nv_bfloat16& h, __nv_bfloat16& l) {
    h = __float2bfloat16(v);
    l = __float2bfloat16(v - __bfloat162float(h));
}

// ---------------- dtype detection + index normalization ----------------
__global__ void detect_dtype(const unsigned long long* __restrict__ ei) {
    if (threadIdx.x == 0 && blockIdx.x == 0) {
        int is64 = 1;
        for (int i = 0; i < 64; i++)
            if (ei[i] >= (unsigned long long)NN) { is64 = 0; break; }
        g_is64 = is64;
    }
}
__global__ void cvt_edges(const void* __restrict__ ei) {
    int e = blockIdx.x * blockDim.x + threadIdx.x;
    if (e >= NE) return;
    if (g_is64) {
        const long long* p = (const long long*)ei;
        g_src[e] = (int)p[e];
        g_dst[e] = (int)p[NE + e];
    } else {
        const int* p = (const int*)ei;
        g_src[e] = p[e];
        g_dst[e] = p[NE + e];
    }
}
__global__ void cvt_batch_zero(const void* __restrict__ b) {
    int n = blockIdx.x * blockDim.x + threadIdx.x;
    if (n >= NN) return;
    if (g_is64) g_batch[n] = (int)((const long long*)b)[n];
    else        g_batch[n] = ((const int*)b)[n];
    g_cnt[n] = 0;
}

// ---------------- CSR build ----------------
__global__ void cnt_kernel() {
    int e = blockIdx.x * blockDim.x + threadIdx.x;
    if (e < NE) atomicAdd(&g_cnt[g_dst[e]], 1);
}
__global__ void scan1() {
    __shared__ int sm[256];
    int b = blockIdx.x, t = threadIdx.x;
    int i = b * 256 + t;
    int v = (i < NN) ? g_cnt[i] : 0;
    sm[t] = v; __syncthreads();
    for (int o = 1; o < 256; o <<= 1) {
        int u = (t >= o) ? sm[t - o] : 0;
        __syncthreads();
        sm[t] += u;
        __syncthreads();
    }
    if (i < NN) g_off[i] = sm[t] - v;
    if (t == 255) g_bsum[b] = sm[255];
}
__global__ void scan2() {
    __shared__ int sm[512];
    int t = threadIdx.x;
    int v = (t < NBLK) ? g_bsum[t] : 0;
    sm[t] = v; __syncthreads();
    for (int o = 1; o < 512; o <<= 1) {
        int u = (t >= o) ? sm[t - o] : 0;
        __syncthreads();
        sm[t] += u;
        __syncthreads();
    }
    if (t < NBLK) g_boff[t] = sm[t] - v;
}
__global__ void scan3() {
    int i = blockIdx.x * blockDim.x + threadIdx.x;
    if (i < NN) {
        int o = g_off[i] + g_boff[i >> 8];
        g_off[i] = o;
        g_cur[i] = o;
        g_inv[i] = 1.f / fmaxf((float)g_cnt[i], 1.f);
    }
}
__global__ void place_kernel() {
    int e = blockIdx.x * blockDim.x + threadIdx.x;
    if (e < NE) {
        int pos = atomicAdd(&g_cur[g_dst[e]], 1);
        g_csr[pos] = g_src[e];
    }
}

// ---------------- zero / init ----------------
__global__ void zero_stats() {
    int c = threadIdx.x;
    g_sum[c] = 0.0; g_sumsq[c] = 0.0;
}
__global__ void init_pool() {
    int i = blockIdx.x * blockDim.x + threadIdx.x;
    if (i < NG * HID) g_pooled[i] = 0.f;
    if (i < NG) { g_smax[i] = -3.4e38f; g_denom[i] = 0.f; }
}

// ---------------- split x (f32 -> bf16 hi/lo, zero-padded to KP0), layer 0 only ----------------
__global__ void split_a(const float* __restrict__ A) {
    int kp2 = KP0 >> 1;
    int i = blockIdx.x * blockDim.x + threadIdx.x;
    if (i >= NN * kp2) return;
    int n = i / kp2, k2 = (i - n * kp2) * 2;
    float v0 = (k2 < IND)     ? A[(size_t)n * IND + k2]     : 0.f;
    float v1 = (k2 + 1 < IND) ? A[(size_t)n * IND + k2 + 1] : 0.f;
    __nv_bfloat162 hp, lp;
    split1(v0, hp.x, lp.x);
    split1(v1, hp.y, lp.y);
    *(__nv_bfloat162*)(g_ah + (size_t)n * KP0 + k2) = hp;
    *(__nv_bfloat162*)(g_al + (size_t)n * KP0 + k2) = lp;
}

// ---------------- pack [Wl|Wr]^T into [512 rows x KP] bf16 hi/lo ----------------
__global__ void pack_wbT(const float* __restrict__ Wl, const float* __restrict__ Wr,
                         int K, int KP) {
    int kp2 = KP >> 1;
    int i = blockIdx.x * blockDim.x + threadIdx.x;
    if (i >= 512 * kp2) return;
    int n = i / kp2, k2 = (i - n * kp2) * 2;
    const float* W = (n < 256) ? Wl : Wr;
    int c = (n < 256) ? n : n - 256;
    float v0 = (k2 < K)     ? W[(size_t)k2 * 256 + c]       : 0.f;
    float v1 = (k2 + 1 < K) ? W[(size_t)(k2 + 1) * 256 + c] : 0.f;
    __nv_bfloat162 hp, lp;
    split1(v0, hp.x, lp.x);
    split1(v1, hp.y, lp.y);
    *(__nv_bfloat162*)(g_bh + (size_t)n * KP + k2) = hp;
    *(__nv_bfloat162*)(g_bl + (size_t)n * KP + k2) = lp;
}

// ---------------- pack Wa1^T [128 rows x 256] bf16 hi/lo (score GEMM B) ----------------
__global__ void pack_wa(const float* __restrict__ Wa1) {
    int i = blockIdx.x * blockDim.x + threadIdx.x;   // 128*128 iters (2 k per it)
    if (i >= 128 * 128) return;
    int n = i >> 7, k2 = (i & 127) * 2;
    float v0 = Wa1[(size_t)k2 * 128 + n];
    float v1 = Wa1[(size_t)(k2 + 1) * 128 + n];
    __nv_bfloat162 hp, lp;
    split1(v0, hp.x, lp.x);
    split1(v1, hp.y, lp.y);
    *(__nv_bfloat162*)(g_bh + (size_t)n * 256 + k2) = hp;
    *(__nv_bfloat162*)(g_bl + (size_t)n * 256 + k2) = lp;
}

// ---------------- split-bf16 GEMM via mma.sync ----------------
// out cols [0,256) -> g_yl, [256,512) -> g_yr  (row stride 256 each)
__global__ __launch_bounds__(128) void gemm_tc(int KP) {
    __shared__ __align__(128) char sm_[24576];
    const uint32_t sb = smem_u32(sm_);   // A_hi 0 | A_lo 8192 | B_hi 16384 | B_lo 20480
    int tid = threadIdx.x, lane = tid & 31, wid = tid >> 5;
    int wm = wid >> 1, wn = wid & 1;
    int row0 = blockIdx.y * 128;
    int col0 = blockIdx.x * 64;
    int nch = KP >> 5;

    float acc[4][4][4];
#pragma unroll
    for (int a = 0; a < 4; a++)
#pragma unroll
        for (int b = 0; b < 4; b++)
#pragma unroll
            for (int c = 0; c < 4; c++) acc[a][b][c] = 0.f;

    for (int ch = 0; ch < nch; ch++) {
        __syncthreads();
#pragma unroll
        for (int i = 0; i < 8; i++) {
            int idx = i * 128 + tid;
            int half = idx >> 9, seg = idx & 511;
            int r = seg >> 2, s = (seg & 3) * 16;
            int gr = row0 + r;
            float4 v = make_float4(0.f, 0.f, 0.f, 0.f);
            if (gr < NN) {
                const char* base = (const char*)(half ? g_al : g_ah);
                v = *(const float4*)(base + ((size_t)gr * KP + ch * 32) * 2 + s);
            }
            uint32_t b = (uint32_t)(r * 64 + s);
            sts128(sb + half * 8192 + SWZ(b), v);
        }
#pragma unroll
        for (int i = 0; i < 4; i++) {
            int idx = i * 128 + tid;
            int half = idx >> 8, seg = idx & 255;
            int r = seg >> 2, s = (seg & 3) * 16;
            int gn = col0 + r;
            const char* base = (const char*)(half ? g_bl : g_bh);
            float4 v = *(const float4*)(base + ((size_t)gn * KP + ch * 32) * 2 + s);
            uint32_t b = (uint32_t)(r * 64 + s);
            sts128(sb + 16384 + half * 4096 + SWZ(b), v);
        }
        __syncthreads();

        int q = lane >> 3, lr = lane & 7;
#pragma unroll
        for (int ks = 0; ks < 2; ks++) {
            uint32_t Ah[4][4], Al[4][4], Bh[2][4], Bl[2][4];
#pragma unroll
            for (int mi = 0; mi < 4; mi++) {
                int row = wm * 64 + mi * 16 + (q & 1) * 8 + lr;
                uint32_t b = (uint32_t)(row * 64 + ks * 32 + (q >> 1) * 16);
                uint32_t a = sb + SWZ(b);
                ldsm4(Ah[mi], a);
                ldsm4(Al[mi], a + 8192);
            }
#pragma unroll
            for (int p = 0; p < 2; p++) {
                int nrow = wn * 32 + p * 16 + (q >> 1) * 8 + lr;
                uint32_t b = (uint32_t)(nrow * 64 + ks * 32 + (q & 1) * 16);
                uint32_t a = sb + 16384 + SWZ(b);
                ldsm4(Bh[p], a);
                ldsm4(Bl[p], a + 4096);
            }
#pragma unroll
            for (int mi = 0; mi < 4; mi++)
#pragma unroll
                for (int ni = 0; ni < 4; ni++) {
                    uint32_t bh0 = Bh[ni >> 1][(ni & 1) * 2], bh1 = Bh[ni >> 1][(ni & 1) * 2 + 1];
                    uint32_t bl0 = Bl[ni >> 1][(ni & 1) * 2], bl1 = Bl[ni >> 1][(ni & 1) * 2 + 1];
                    mma_bf16(acc[mi][ni], Ah[mi], bh0, bh1);
                    mma_bf16(acc[mi][ni], Al[mi], bh0, bh1);
                    mma_bf16(acc[mi][ni], Ah[mi], bl0, bl1);
                }
        }
    }

    float* dstbase = (col0 < 256) ? g_yl : g_yr;
    int cb = col0 & 255;
    int tr = lane >> 2, tc = lane & 3;
#pragma unroll
    for (int mi = 0; mi < 4; mi++)
#pragma unroll
        for (int half = 0; half < 2; half++) {
            int row = row0 + wm * 64 + mi * 16 + tr + half * 8;
            if (row < NN) {
                float* p = dstbase + (size_t)row * 256 + cb + wn * 32 + tc * 2;
#pragma unroll
                for (int ni = 0; ni < 4; ni++) {
                    float2 v = make_float2(acc[mi][ni][half * 2], acc[mi][ni][half * 2 + 1]);
                    *(float2*)(p + ni * 8) = v;
                }
            }
        }
}

// ---------------- CSR aggregation + combine + BN stats ----------------
__global__ __launch_bounds__(256) void agg_combine(const float* __restrict__ bl) {
    int c  = threadIdx.x;
    int r0 = blockIdx.x * 64;
    int r1 = min(r0 + 64, NN);
    float bias = bl[c];
    float s = 0.f, s2 = 0.f;
    for (int r = r0; r < r1; r++) {
        int beg = g_off[r];
        int end = (r == NN - 1) ? NE : g_off[r + 1];
        float acc = 0.f;
        for (int i = beg; i < end; i++) {
            int src = g_csr[i];
            acc += g_yl[(size_t)src * 256 + c];
        }
        float pre = acc * g_inv[r] + bias + g_yr[(size_t)r * 256 + c];
        g_m[(size_t)r * 256 + c] = pre;
        s += pre; s2 += pre * pre;
    }
    atomicAdd(&g_sum[c], (double)s);
    atomicAdd(&g_sumsq[c], (double)s2);
}

__global__ void finalize_bn(const float* __restrict__ gm, const float* __restrict__ bt) {
    int c = threadIdx.x;
    double mean = g_sum[c] / (double)NN;
    double var  = g_sumsq[c] / (double)NN - mean * mean;
    float rstd  = rsqrtf((float)var + 1e-5f);
    float sc    = rstd * gm[c];
    g_scale[c]  = sc;
    g_shift[c]  = bt[c] - (float)mean * sc;
}

// mode 1: bf16 hi/lo only (layers 0,1); mode 2: bf16 + fp32 g_h (layer 2)
__global__ void bnrelu(int mode) {
    size_t i = (size_t)blockIdx.x * blockDim.x + threadIdx.x;
    if (i >= (size_t)NN * 64) return;
    size_t idx = i * 4;
    int c = (int)(idx & 255);
    float4 v = *(const float4*)(g_m + idx);
    v.x = fmaxf(v.x * g_scale[c + 0] + g_shift[c + 0], 0.f);
    v.y = fmaxf(v.y * g_scale[c + 1] + g_shift[c + 1], 0.f);
    v.z = fmaxf(v.z * g_scale[c + 2] + g_shift[c + 2], 0.f);
    v.w = fmaxf(v.w * g_scale[c + 3] + g_shift[c + 3], 0.f);
    __nv_bfloat162 h01, l01, h23, l23;
    split1(v.x, h01.x, l01.x);
    split1(v.y, h01.y, l01.y);
    split1(v.z, h23.x, l23.x);
    split1(v.w, h23.y, l23.y);
    uint2 uh, ul;
    uh.x = *(uint32_t*)&h01; uh.y = *(uint32_t*)&h23;
    ul.x = *(uint32_t*)&l01; ul.y = *(uint32_t*)&l23;
    *(uint2*)(g_ah + idx) = uh;
    *(uint2*)(g_al + idx) = ul;
    if (mode == 2) *(float4*)(g_h + idx) = v;
}

// ---------------- tanh-dot: s[n] = ba2 + sum_j tanh(S[n,j]+ba1[j])*Wa2[j] ----------------
__global__ __launch_bounds__(256) void tanhdot(const float* __restrict__ ba1,
                                               const float* __restrict__ Wa2,
                                               const float* __restrict__ ba2) {
    __shared__ float red[2][4];
    int tid = threadIdx.x, sub = tid >> 7, j = tid & 127;
    int n = blockIdx.x * 2 + sub;
    float t = 0.f;
    if (n < NN)
        t = tanhf(g_yl[(size_t)n * 256 + j] + ba1[j]) * Wa2[j];
#pragma unroll
    for (int o = 16; o; o >>= 1) t += __shfl_down_sync(0xffffffffu, t, o);
    if ((j & 31) == 0) red[sub][j >> 5] = t;
    __syncthreads();
    if (j == 0 && n < NN)
        g_s[n] = red[sub][0] + red[sub][1] + red[sub][2] + red[sub][3] + ba2[0];
}

// ---------------- per-graph softmax ----------------
__global__ void segmax_kernel() {
    int n  = blockIdx.x * blockDim.x + threadIdx.x;
    int nc = min(n, NN - 1);
    int g  = g_batch[nc];
    float v = (n < NN) ? g_s[n] : -3.4e38f;
    int g0 = __shfl_sync(0xffffffffu, g, 0);
    bool uni = __all_sync(0xffffffffu, g == g0);
    if (uni) {
#pragma unroll
        for (int o = 16; o; o >>= 1) v = fmaxf(v, __shfl_down_sync(0xffffffffu, v, o));
        if ((threadIdx.x & 31) == 0) atomicMaxFloat(&g_smax[g0], v);
    } else if (n < NN) {
        atomicMaxFloat(&g_smax[g], v);
    }
}

__global__ void expsum_kernel() {
    int n  = blockIdx.x * blockDim.x + threadIdx.x;
    int nc = min(n, NN - 1);
    int g  = g_batch[nc];
    float e = 0.f;
    if (n < NN) { e = expf(g_s[n] - g_smax[g]); g_w[n] = e; }
    int g0 = __shfl_sync(0xffffffffu, g, 0);
    bool uni = __all_sync(0xffffffffu, g == g0);
    if (uni) {
#pragma unroll
        for (int o = 16; o; o >>= 1) e += __shfl_down_sync(0xffffffffu, e, o);
        if ((threadIdx.x & 31) == 0) atomicAdd(&g_denom[g0], e);
    } else if (n < NN) {
        atomicAdd(&g_denom[g], e);
    }
}

__global__ void weights_kernel() {
    int n = blockIdx.x * blockDim.x + threadIdx.x;
    if (n < NN) g_w[n] = g_w[n] / g_denom[g_batch[n]];
}

// ---------------- weighted pooling ----------------
__global__ void pooled_kernel() {
    int c  = threadIdx.x;
    int r0 = blockIdx.x * 512;
    if (r0 >= NN) return;
    int r1  = min(r0 + 512, NN);
    int cur = g_batch[r0];
    float acc = 0.f;
    for (int r = r0; r < r1; r++) {
        int g = g_batch[r];
        if (g != cur) { atomicAdd(&g_pooled[cur * 256 + c], acc); acc = 0.f; cur = g; }
        acc += g_h[(size_t)r * 256 + c] * g_w[r];
    }
    atomicAdd(&g_pooled[cur * 256 + c], acc);
}

// ---------------- classifier ----------------
__global__ void classifier_kernel(const float* __restrict__ Wc1, const float* __restrict__ bc1,
                                  const float* __restrict__ Wc2, const float* __restrict__ bc2,
                                  float* __restrict__ out) {
    int g = blockIdx.x;
    int j = threadIdx.x;
    float acc = bc1[j];
    for (int k = 0; k < 256; k++) acc += g_pooled[g * 256 + k] * Wc1[k * 128 + j];
    float t = fmaxf(acc, 0.f) * Wc2[j];
#pragma unroll
    for (int o = 16; o; o >>= 1) t += __shfl_down_sync(0xffffffffu, t, o);
    __shared__ float red[4];
    if ((j & 31) == 0) red[j >> 5] = t;
    __syncthreads();
    if (j == 0) out[g] = red[0] + red[1] + red[2] + red[3] + bc2[0];
}

// ---------------- launch ----------------
extern "C" void kernel_launch(void* const* d_in, const int* in_sizes, int n_in,
                              void* d_out, int out_size) {
    const float* x     = (const float*)d_in[0];
    const void*  ei    = d_in[1];
    const void*  batch = d_in[2];
    const float* Wl[3] = {(const float*)d_in[3], (const float*)d_in[8],  (const float*)d_in[13]};
    const float* bl[3] = {(const float*)d_in[4], (const float*)d_in[9],  (const float*)d_in[14]};
    const float* Wr[3] = {(const float*)d_in[5], (const float*)d_in[10], (const float*)d_in[15]};
    const float* gg[3] = {(const float*)d_in[6], (const float*)d_in[11], (const float*)d_in[16]};
    const float* bb[3] = {(const float*)d_in[7], (const float*)d_in[12], (const float*)d_in[17]};
    const float* Wa1 = (const float*)d_in[18];
    const float* ba1 = (const float*)d_in[19];
    const float* Wa2 = (const float*)d_in[20];
    const float* ba2 = (const float*)d_in[21];
    const float* Wc1 = (const float*)d_in[22];
    const float* bc1 = (const float*)d_in[23];
    const float* Wc2 = (const float*)d_in[24];
    const float* bc2 = (const float*)d_in[25];
    float* out = (float*)d_out;

    // launches 1-4: layer-0 GEMM path first (4th launch = gemm_tc -> ncu capture slot)
    detect_dtype<<<1, 32>>>((const unsigned long long*)ei);
    split_a<<<(NN * (KP0 / 2) + 255) / 256, 256>>>(x);
    pack_wbT<<<(512 * (KP0 / 2) + 255) / 256, 256>>>(Wl[0], Wr[0], IND, KP0);
    {
        dim3 ggrid(8, (NN + 127) / 128);
        gemm_tc<<<ggrid, 128>>>(KP0);
    }

    // graph preprocessing
    cvt_edges<<<(NE + 255) / 256, 256>>>(ei);
    cvt_batch_zero<<<(NN + 255) / 256, 256>>>(batch);
    cnt_kernel<<<(NE + 255) / 256, 256>>>();
    scan1<<<NBLK, 256>>>();
    scan2<<<1, 512>>>();
    scan3<<<(NN + 255) / 256, 256>>>();
    place_kernel<<<(NE + 255) / 256, 256>>>();

    for (int L = 0; L < 3; L++) {
        if (L > 0) {
            pack_wbT<<<(512 * (HID / 2) + 255) / 256, 256>>>(Wl[L], Wr[L], HID, HID);
            dim3 ggrid(8, (NN + 127) / 128);
            gemm_tc<<<ggrid, 128>>>(HID);
        }
        zero_stats<<<1, 256>>>();
        agg_combine<<<(NN + 63) / 64, 256>>>(bl[L]);
        finalize_bn<<<1, 256>>>(gg[L], bb[L]);
        bnrelu<<<(NN * 64 + 255) / 256, 256>>>(L < 2 ? 1 : 2);
    }

    // attention score: S = h @ Wa1 via tensor GEMM (N=128, into g_yl), then tanh-dot
    pack_wa<<<(128 * 128 + 255) / 256, 256>>>(Wa1);
    {
        dim3 sgrid(2, (NN + 127) / 128);
        gemm_tc<<<sgrid, 128>>>(HID);
    }
    tanhdot<<<(NN + 1) / 2, 256>>>(ba1, Wa2, ba2);

    init_pool<<<(NG * HID + 255) / 256, 256>>>();
    segmax_kernel<<<(NN + 255) / 256, 256>>>();
    expsum_kernel<<<(NN + 255) / 256, 256>>>();
    weights_kernel<<<(NN + 255) / 256, 256>>>();
    pooled_kernel<<<(NN + 511) / 512, 256>>>();
    classifier_kernel<<<NG, 128>>>(Wc1, bc1, Wc2, bc2, out);
}

// round 8
// speedup vs baseline: 2.5565x; 1.0545x over previous
#include <cuda_runtime.h>
#include <cuda_bf16.h>
#include <math.h>
#include <stdint.h>

#define NN 100000
#define NE 400000
#define IND 771
#define HID 256
#define NG 64
#define KP0 800            // padded K for layer 0
#define NBLK 391           // ceil(NN/256)

// ---------------- scratch (static device globals; no allocation) ----------------
__device__ float  g_yl[(size_t)NN * 256];    // lin_l pre-agg (also score-GEMM scratch)
__device__ float  g_yr[(size_t)NN * 256];    // lin_r part
__device__ float  g_m[(size_t)NN * 256];     // pre-BN
__device__ float  g_h[(size_t)NN * 256];     // final layer output
__device__ float  g_inv[NN];
__device__ double g_sum[256];
__device__ double g_sumsq[256];
__device__ float  g_scale[256];
__device__ float  g_shift[256];
__device__ float  g_s[NN];
__device__ float  g_w[NN];
__device__ float  g_smax[NG];
__device__ float  g_denom[NG];
__device__ float  g_pooled[NG * HID];
__device__ int    g_is64;
__device__ int    g_src[NE];
__device__ int    g_dst[NE];
__device__ int    g_batch[NN];
// CSR by dst
__device__ int    g_cnt[NN];
__device__ int    g_off[NN];
__device__ int    g_cur[NN];
__device__ int    g_csr[NE];
__device__ int    g_bsum[NBLK];
__device__ int    g_boff[NBLK];
// bf16 split operands
__device__ __nv_bfloat16 g_ah[(size_t)NN * KP0];
__device__ __nv_bfloat16 g_al[(size_t)NN * KP0];
__device__ __nv_bfloat16 g_bh[512 * KP0];
__device__ __nv_bfloat16 g_bl[512 * KP0];

// ---------------- helpers ----------------
__device__ __forceinline__ uint32_t smem_u32(const void* p) {
    uint32_t a;
    asm("{ .reg .u64 t; cvta.to.shared.u64 t, %1; cvt.u32.u64 %0, t; }" : "=r"(a) : "l"(p));
    return a;
}
// 16-row x 32B tiles: toggle 16B half by (row>>2)&1 -> conflict-free ldmatrix + stores
#define SWZ16(b) ((b) ^ ((((b) >> 7) & 1) << 4))

__device__ __forceinline__ void cpasync16(uint32_t dst, const void* src, bool pred) {
    int sz = pred ? 16 : 0;
    asm volatile("cp.async.cg.shared.global [%0], [%1], 16, %2;"
                 :: "r"(dst), "l"(src), "r"(sz) : "memory");
}
__device__ __forceinline__ void cp_commit() {
    asm volatile("cp.async.commit_group;" ::: "memory");
}
__device__ __forceinline__ void cp_wait1() {
    asm volatile("cp.async.wait_group 1;" ::: "memory");
}
__device__ __forceinline__ void ldsm4(uint32_t* r, uint32_t addr) {
    asm volatile("ldmatrix.sync.aligned.m8n8.x4.shared.b16 {%0,%1,%2,%3}, [%4];"
                 : "=r"(r[0]), "=r"(r[1]), "=r"(r[2]), "=r"(r[3]) : "r"(addr));
}
__device__ __forceinline__ void mma_bf16(float* c, const uint32_t* a, uint32_t b0, uint32_t b1) {
    asm volatile(
        "mma.sync.aligned.m16n8k16.row.col.f32.bf16.bf16.f32 "
        "{%0,%1,%2,%3}, {%4,%5,%6,%7}, {%8,%9}, {%0,%1,%2,%3};"
        : "+f"(c[0]), "+f"(c[1]), "+f"(c[2]), "+f"(c[3])
        : "r"(a[0]), "r"(a[1]), "r"(a[2]), "r"(a[3]), "r"(b0), "r"(b1));
}
__device__ __forceinline__ void atomicMaxFloat(float* addr, float val) {
    int* ai = (int*)addr;
    int old = __float_as_int(*addr);
    while (__int_as_float(old) < val) {
        int assumed = old;
        old = atomicCAS(ai, assumed, __float_as_int(val));
        if (old == assumed) break;
    }
}
__device__ __forceinline__ void split1(float v, __nv_bfloat16& h, __nv_bfloat16& l) {
    h = __float2bfloat16(v);
    l = __float2bfloat16(v - __bfloat162float(h));
}

// ---------------- dtype detection + index normalization ----------------
__global__ void detect_dtype(const unsigned long long* __restrict__ ei) {
    if (threadIdx.x == 0 && blockIdx.x == 0) {
        int is64 = 1;
        for (int i = 0; i < 64; i++)
            if (ei[i] >= (unsigned long long)NN) { is64 = 0; break; }
        g_is64 = is64;
    }
}
__global__ void cvt_edges(const void* __restrict__ ei) {
    int e = blockIdx.x * blockDim.x + threadIdx.x;
    if (e >= NE) return;
    if (g_is64) {
        const long long* p = (const long long*)ei;
        g_src[e] = (int)p[e];
        g_dst[e] = (int)p[NE + e];
    } else {
        const int* p = (const int*)ei;
        g_src[e] = p[e];
        g_dst[e] = p[NE + e];
    }
}
__global__ void cvt_batch_zero(const void* __restrict__ b) {
    int n = blockIdx.x * blockDim.x + threadIdx.x;
    if (n >= NN) return;
    if (g_is64) g_batch[n] = (int)((const long long*)b)[n];
    else        g_batch[n] = ((const int*)b)[n];
    g_cnt[n] = 0;
}

// ---------------- CSR build ----------------
__global__ void cnt_kernel() {
    int e = blockIdx.x * blockDim.x + threadIdx.x;
    if (e < NE) atomicAdd(&g_cnt[g_dst[e]], 1);
}
__global__ void scan1() {
    __shared__ int sm[256];
    int b = blockIdx.x, t = threadIdx.x;
    int i = b * 256 + t;
    int v = (i < NN) ? g_cnt[i] : 0;
    sm[t] = v; __syncthreads();
    for (int o = 1; o < 256; o <<= 1) {
        int u = (t >= o) ? sm[t - o] : 0;
        __syncthreads();
        sm[t] += u;
        __syncthreads();
    }
    if (i < NN) g_off[i] = sm[t] - v;
    if (t == 255) g_bsum[b] = sm[255];
}
__global__ void scan2() {
    __shared__ int sm[512];
    int t = threadIdx.x;
    int v = (t < NBLK) ? g_bsum[t] : 0;
    sm[t] = v; __syncthreads();
    for (int o = 1; o < 512; o <<= 1) {
        int u = (t >= o) ? sm[t - o] : 0;
        __syncthreads();
        sm[t] += u;
        __syncthreads();
    }
    if (t < NBLK) g_boff[t] = sm[t] - v;
}
__global__ void scan3() {
    int i = blockIdx.x * blockDim.x + threadIdx.x;
    if (i < NN) {
        int o = g_off[i] + g_boff[i >> 8];
        g_off[i] = o;
        g_cur[i] = o;
        g_inv[i] = 1.f / fmaxf((float)g_cnt[i], 1.f);
    }
}
__global__ void place_kernel() {
    int e = blockIdx.x * blockDim.x + threadIdx.x;
    if (e < NE) {
        int pos = atomicAdd(&g_cur[g_dst[e]], 1);
        g_csr[pos] = g_src[e];
    }
}

// ---------------- zero / init ----------------
__global__ void zero_stats() {
    int c = threadIdx.x;
    g_sum[c] = 0.0; g_sumsq[c] = 0.0;
}
__global__ void init_pool() {
    int i = blockIdx.x * blockDim.x + threadIdx.x;
    if (i < NG * HID) g_pooled[i] = 0.f;
    if (i < NG) { g_smax[i] = -3.4e38f; g_denom[i] = 0.f; }
}

// ---------------- split x (layer 0 only) ----------------
__global__ void split_a(const float* __restrict__ A) {
    int kp2 = KP0 >> 1;
    int i = blockIdx.x * blockDim.x + threadIdx.x;
    if (i >= NN * kp2) return;
    int n = i / kp2, k2 = (i - n * kp2) * 2;
    float v0 = (k2 < IND)     ? A[(size_t)n * IND + k2]     : 0.f;
    float v1 = (k2 + 1 < IND) ? A[(size_t)n * IND + k2 + 1] : 0.f;
    __nv_bfloat162 hp, lp;
    split1(v0, hp.x, lp.x);
    split1(v1, hp.y, lp.y);
    *(__nv_bfloat162*)(g_ah + (size_t)n * KP0 + k2) = hp;
    *(__nv_bfloat162*)(g_al + (size_t)n * KP0 + k2) = lp;
}

// ---------------- pack [Wl|Wr]^T ----------------
__global__ void pack_wbT(const float* __restrict__ Wl, const float* __restrict__ Wr,
                         int K, int KP) {
    int kp2 = KP >> 1;
    int i = blockIdx.x * blockDim.x + threadIdx.x;
    if (i >= 512 * kp2) return;
    int n = i / kp2, k2 = (i - n * kp2) * 2;
    const float* W = (n < 256) ? Wl : Wr;
    int c = (n < 256) ? n : n - 256;
    float v0 = (k2 < K)     ? W[(size_t)k2 * 256 + c]       : 0.f;
    float v1 = (k2 + 1 < K) ? W[(size_t)(k2 + 1) * 256 + c] : 0.f;
    __nv_bfloat162 hp, lp;
    split1(v0, hp.x, lp.x);
    split1(v1, hp.y, lp.y);
    *(__nv_bfloat162*)(g_bh + (size_t)n * KP + k2) = hp;
    *(__nv_bfloat162*)(g_bl + (size_t)n * KP + k2) = lp;
}

// ---------------- pack Wa1^T (score GEMM B) ----------------
__global__ void pack_wa(const float* __restrict__ Wa1) {
    int i = blockIdx.x * blockDim.x + threadIdx.x;
    if (i >= 128 * 128) return;
    int n = i >> 7, k2 = (i & 127) * 2;
    float v0 = Wa1[(size_t)k2 * 128 + n];
    float v1 = Wa1[(size_t)(k2 + 1) * 128 + n];
    __nv_bfloat162 hp, lp;
    split1(v0, hp.x, lp.x);
    split1(v1, hp.y, lp.y);
    *(__nv_bfloat162*)(g_bh + (size_t)n * 256 + k2) = hp;
    *(__nv_bfloat162*)(g_bl + (size_t)n * 256 + k2) = lp;
}

// ---------------- split-bf16 GEMM: M128 x N128 tile, 8 warps, k16 chunks, 2-stage cp.async ----
// stage (16KB): A_hi 0 | A_lo 4096 | B_hi 8192 | B_lo 12288
__global__ __launch_bounds__(256) void gemm_tc(int KP) {
    __shared__ __align__(128) char sm_[32768];
    const uint32_t sb = smem_u32(sm_);
    int tid = threadIdx.x, lane = tid & 31, wid = tid >> 5;
    int wm = wid >> 2, wn = wid & 3;         // 2 x 4 warps, warp tile 64x32
    int row0 = blockIdx.y * 128;
    int col0 = blockIdx.x * 128;
    int nch = KP >> 4;

    float acc[4][4][4];
#pragma unroll
    for (int a = 0; a < 4; a++)
#pragma unroll
        for (int b = 0; b < 4; b++)
#pragma unroll
            for (int c = 0; c < 4; c++) acc[a][b][c] = 0.f;

    // staging lambda-ish macro: each thread moves 2x16B for A and 2x16B for B
#define STAGE(CH, BUF)                                                                   \
    do {                                                                                 \
        uint32_t stg = sb + (BUF) * 16384;                                               \
        _Pragma("unroll")                                                                \
        for (int i = 0; i < 2; i++) {                                                    \
            int idx = i * 256 + tid;                                                     \
            int half = idx >> 8, seg = idx & 255;                                        \
            int r = seg >> 1, s16 = (seg & 1) * 16;                                      \
            int gr = row0 + r;                                                           \
            const char* srcA = (const char*)(half ? g_al : g_ah) +                       \
                               ((size_t)gr * KP + (CH) * 16) * 2 + s16;                  \
            cpasync16(stg + half * 4096 + SWZ16((uint32_t)(r * 32 + s16)), srcA, gr < NN); \
            int gn = col0 + r;                                                           \
            const char* srcB = (const char*)(half ? g_bl : g_bh) +                       \
                               ((size_t)gn * KP + (CH) * 16) * 2 + s16;                  \
            cpasync16(stg + 8192 + half * 4096 + SWZ16((uint32_t)(r * 32 + s16)), srcB, true); \
        }                                                                                \
    } while (0)

    STAGE(0, 0);
    cp_commit();

    int q = lane >> 3, lr = lane & 7;
    for (int ch = 0; ch < nch; ch++) {
        if (ch + 1 < nch) STAGE(ch + 1, (ch + 1) & 1);
        cp_commit();
        cp_wait1();
        __syncthreads();

        uint32_t stg = sb + (ch & 1) * 16384;
        uint32_t Ah[4][4], Al[4][4], Bh[2][4], Bl[2][4];
#pragma unroll
        for (int mi = 0; mi < 4; mi++) {
            int row = wm * 64 + mi * 16 + (q & 1) * 8 + lr;
            uint32_t b = (uint32_t)(row * 32 + (q >> 1) * 16);
            uint32_t a = stg + SWZ16(b);
            ldsm4(Ah[mi], a);
            ldsm4(Al[mi], a + 4096);
        }
#pragma unroll
        for (int p = 0; p < 2; p++) {
            int nrow = wn * 32 + p * 16 + (q >> 1) * 8 + lr;
            uint32_t b = (uint32_t)(nrow * 32 + (q & 1) * 16);
            uint32_t a = stg + 8192 + SWZ16(b);
            ldsm4(Bh[p], a);
            ldsm4(Bl[p], a + 4096);
        }
#pragma unroll
        for (int mi = 0; mi < 4; mi++)
#pragma unroll
            for (int ni = 0; ni < 4; ni++) {
                uint32_t bh0 = Bh[ni >> 1][(ni & 1) * 2], bh1 = Bh[ni >> 1][(ni & 1) * 2 + 1];
                uint32_t bl0 = Bl[ni >> 1][(ni & 1) * 2], bl1 = Bl[ni >> 1][(ni & 1) * 2 + 1];
                mma_bf16(acc[mi][ni], Ah[mi], bh0, bh1);
                mma_bf16(acc[mi][ni], Al[mi], bh0, bh1);
                mma_bf16(acc[mi][ni], Ah[mi], bl0, bl1);
            }
        __syncthreads();
    }
#undef STAGE

    float* dstbase = (col0 < 256) ? g_yl : g_yr;
    int cb = col0 & 255;
    int tr = lane >> 2, tc = lane & 3;
#pragma unroll
    for (int mi = 0; mi < 4; mi++)
#pragma unroll
        for (int half = 0; half < 2; half++) {
            int row = row0 + wm * 64 + mi * 16 + tr + half * 8;
            if (row < NN) {
                float* p = dstbase + (size_t)row * 256 + cb + wn * 32 + tc * 2;
#pragma unroll
                for (int ni = 0; ni < 4; ni++) {
                    float2 v = make_float2(acc[mi][ni][half * 2], acc[mi][ni][half * 2 + 1]);
                    *(float2*)(p + ni * 8) = v;
                }
            }
        }
}

// ---------------- CSR aggregation + combine + BN stats (unroll-4 MLP) ----------------
__global__ __launch_bounds__(256) void agg_combine(const float* __restrict__ bl) {
    int c  = threadIdx.x;
    int r0 = blockIdx.x * 32;
    if (r0 >= NN) return;
    int r1 = min(r0 + 32, NN);
    float bias = bl[c];
    float s = 0.f, s2 = 0.f;
    for (int r = r0; r < r1; r++) {
        int beg = g_off[r];
        int end = (r == NN - 1) ? NE : g_off[r + 1];
        float a0 = 0.f, a1 = 0.f, a2 = 0.f, a3 = 0.f;
        int i = beg;
        for (; i + 4 <= end; i += 4) {
            int s0 = g_csr[i], s1 = g_csr[i + 1], s2i = g_csr[i + 2], s3 = g_csr[i + 3];
            float v0 = g_yl[(size_t)s0 * 256 + c];
            float v1 = g_yl[(size_t)s1 * 256 + c];
            float v2 = g_yl[(size_t)s2i * 256 + c];
            float v3 = g_yl[(size_t)s3 * 256 + c];
            a0 += v0; a1 += v1; a2 += v2; a3 += v3;
        }
        for (; i < end; i++) a0 += g_yl[(size_t)g_csr[i] * 256 + c];
        float acc = (a0 + a1) + (a2 + a3);
        float pre = acc * g_inv[r] + bias + g_yr[(size_t)r * 256 + c];
        g_m[(size_t)r * 256 + c] = pre;
        s += pre; s2 += pre * pre;
    }
    atomicAdd(&g_sum[c], (double)s);
    atomicAdd(&g_sumsq[c], (double)s2);
}

__global__ void finalize_bn(const float* __restrict__ gm, const float* __restrict__ bt) {
    int c = threadIdx.x;
    double mean = g_sum[c] / (double)NN;
    double var  = g_sumsq[c] / (double)NN - mean * mean;
    float rstd  = rsqrtf((float)var + 1e-5f);
    float sc    = rstd * gm[c];
    g_scale[c]  = sc;
    g_shift[c]  = bt[c] - (float)mean * sc;
}

// mode 1: bf16 hi/lo only; mode 2: bf16 + fp32 g_h
__global__ void bnrelu(int mode) {
    size_t i = (size_t)blockIdx.x * blockDim.x + threadIdx.x;
    if (i >= (size_t)NN * 64) return;
    size_t idx = i * 4;
    int c = (int)(idx & 255);
    float4 v = *(const float4*)(g_m + idx);
    v.x = fmaxf(v.x * g_scale[c + 0] + g_shift[c + 0], 0.f);
    v.y = fmaxf(v.y * g_scale[c + 1] + g_shift[c + 1], 0.f);
    v.z = fmaxf(v.z * g_scale[c + 2] + g_shift[c + 2], 0.f);
    v.w = fmaxf(v.w * g_scale[c + 3] + g_shift[c + 3], 0.f);
    __nv_bfloat162 h01, l01, h23, l23;
    split1(v.x, h01.x, l01.x);
    split1(v.y, h01.y, l01.y);
    split1(v.z, h23.x, l23.x);
    split1(v.w, h23.y, l23.y);
    uint2 uh, ul;
    uh.x = *(uint32_t*)&h01; uh.y = *(uint32_t*)&h23;
    ul.x = *(uint32_t*)&l01; ul.y = *(uint32_t*)&l23;
    *(uint2*)(g_ah + idx) = uh;
    *(uint2*)(g_al + idx) = ul;
    if (mode == 2) *(float4*)(g_h + idx) = v;
}

// ---------------- tanh-dot ----------------
__global__ __launch_bounds__(256) void tanhdot(const float* __restrict__ ba1,
                                               const float* __restrict__ Wa2,
                                               const float* __restrict__ ba2) {
    __shared__ float red[2][4];
    int tid = threadIdx.x, sub = tid >> 7, j = tid & 127;
    int n = blockIdx.x * 2 + sub;
    float t = 0.f;
    if (n < NN)
        t = tanhf(g_yl[(size_t)n * 256 + j] + ba1[j]) * Wa2[j];
#pragma unroll
    for (int o = 16; o; o >>= 1) t += __shfl_down_sync(0xffffffffu, t, o);
    if ((j & 31) == 0) red[sub][j >> 5] = t;
    __syncthreads();
    if (j == 0 && n < NN)
        g_s[n] = red[sub][0] + red[sub][1] + red[sub][2] + red[sub][3] + ba2[0];
}

// ---------------- per-graph softmax ----------------
__global__ void segmax_kernel() {
    int n  = blockIdx.x * blockDim.x + threadIdx.x;
    int nc = min(n, NN - 1);
    int g  = g_batch[nc];
    float v = (n < NN) ? g_s[n] : -3.4e38f;
    int g0 = __shfl_sync(0xffffffffu, g, 0);
    bool uni = __all_sync(0xffffffffu, g == g0);
    if (uni) {
#pragma unroll
        for (int o = 16; o; o >>= 1) v = fmaxf(v, __shfl_down_sync(0xffffffffu, v, o));
        if ((threadIdx.x & 31) == 0) atomicMaxFloat(&g_smax[g0], v);
    } else if (n < NN) {
        atomicMaxFloat(&g_smax[g], v);
    }
}

__global__ void expsum_kernel() {
    int n  = blockIdx.x * blockDim.x + threadIdx.x;
    int nc = min(n, NN - 1);
    int g  = g_batch[nc];
    float e = 0.f;
    if (n < NN) { e = expf(g_s[n] - g_smax[g]); g_w[n] = e; }
    int g0 = __shfl_sync(0xffffffffu, g, 0);
    bool uni = __all_sync(0xffffffffu, g == g0);
    if (uni) {
#pragma unroll
        for (int o = 16; o; o >>= 1) e += __shfl_down_sync(0xffffffffu, e, o);
        if ((threadIdx.x & 31) == 0) atomicAdd(&g_denom[g0], e);
    } else if (n < NN) {
        atomicAdd(&g_denom[g], e);
    }
}

__global__ void weights_kernel() {
    int n = blockIdx.x * blockDim.x + threadIdx.x;
    if (n < NN) g_w[n] = g_w[n] / g_denom[g_batch[n]];
}

// ---------------- weighted pooling ----------------
__global__ void pooled_kernel() {
    int c  = threadIdx.x;
    int r0 = blockIdx.x * 512;
    if (r0 >= NN) return;
    int r1  = min(r0 + 512, NN);
    int cur = g_batch[r0];
    float acc = 0.f;
    for (int r = r0; r < r1; r++) {
        int g = g_batch[r];
        if (g != cur) { atomicAdd(&g_pooled[cur * 256 + c], acc); acc = 0.f; cur = g; }
        acc += g_h[(size_t)r * 256 + c] * g_w[r];
    }
    atomicAdd(&g_pooled[cur * 256 + c], acc);
}

// ---------------- classifier ----------------
__global__ void classifier_kernel(const float* __restrict__ Wc1, const float* __restrict__ bc1,
                                  const float* __restrict__ Wc2, const float* __restrict__ bc2,
                                  float* __restrict__ out) {
    int g = blockIdx.x;
    int j = threadIdx.x;
    float acc = bc1[j];
    for (int k = 0; k < 256; k++) acc += g_pooled[g * 256 + k] * Wc1[k * 128 + j];
    float t = fmaxf(acc, 0.f) * Wc2[j];
#pragma unroll
    for (int o = 16; o; o >>= 1) t += __shfl_down_sync(0xffffffffu, t, o);
    __shared__ float red[4];
    if ((j & 31) == 0) red[j >> 5] = t;
    __syncthreads();
    if (j == 0) out[g] = red[0] + red[1] + red[2] + red[3] + bc2[0];
}

// ---------------- launch ----------------
extern "C" void kernel_launch(void* const* d_in, const int* in_sizes, int n_in,
                              void* d_out, int out_size) {
    const float* x     = (const float*)d_in[0];
    const void*  ei    = d_in[1];
    const void*  batch = d_in[2];
    const float* Wl[3] = {(const float*)d_in[3], (const float*)d_in[8],  (const float*)d_in[13]};
    const float* bl[3] = {(const float*)d_in[4], (const float*)d_in[9],  (const float*)d_in[14]};
    const float* Wr[3] = {(const float*)d_in[5], (const float*)d_in[10], (const float*)d_in[15]};
    const float* gg[3] = {(const float*)d_in[6], (const float*)d_in[11], (const float*)d_in[16]};
    const float* bb[3] = {(const float*)d_in[7], (const float*)d_in[12], (const float*)d_in[17]};
    const float* Wa1 = (const float*)d_in[18];
    const float* ba1 = (const float*)d_in[19];
    const float* Wa2 = (const float*)d_in[20];
    const float* ba2 = (const float*)d_in[21];
    const float* Wc1 = (const float*)d_in[22];
    const float* bc1 = (const float*)d_in[23];
    const float* Wc2 = (const float*)d_in[24];
    const float* bc2 = (const float*)d_in[25];
    float* out = (float*)d_out;

    // launches 1-4: layer-0 GEMM path first (4th launch = gemm_tc -> ncu capture slot)
    detect_dtype<<<1, 32>>>((const unsigned long long*)ei);
    split_a<<<(NN * (KP0 / 2) + 255) / 256, 256>>>(x);
    pack_wbT<<<(512 * (KP0 / 2) + 255) / 256, 256>>>(Wl[0], Wr[0], IND, KP0);
    {
        dim3 ggrid(4, (NN + 127) / 128);
        gemm_tc<<<ggrid, 256>>>(KP0);
    }

    // graph preprocessing
    cvt_edges<<<(NE + 255) / 256, 256>>>(ei);
    cvt_batch_zero<<<(NN + 255) / 256, 256>>>(batch);
    cnt_kernel<<<(NE + 255) / 256, 256>>>();
    scan1<<<NBLK, 256>>>();
    scan2<<<1, 512>>>();
    scan3<<<(NN + 255) / 256, 256>>>();
    place_kernel<<<(NE + 255) / 256, 256>>>();

    for (int L = 0; L < 3; L++) {
        if (L > 0) {
            pack_wbT<<<(512 * (HID / 2) + 255) / 256, 256>>>(Wl[L], Wr[L], HID, HID);
            dim3 ggrid(4, (NN + 127) / 128);
            gemm_tc<<<ggrid, 256>>>(HID);
        }
        zero_stats<<<1, 256>>>();
        agg_combine<<<(NN + 31) / 32, 256>>>(bl[L]);
        finalize_bn<<<1, 256>>>(gg[L], bb[L]);
        bnrelu<<<(NN * 64 + 255) / 256, 256>>>(L < 2 ? 1 : 2);
    }

    // attention score: S = h @ Wa1 via tensor GEMM (N=128 -> g_yl), then tanh-dot
    pack_wa<<<(128 * 128 + 255) / 256, 256>>>(Wa1);
    {
        dim3 sgrid(1, (NN + 127) / 128);
        gemm_tc<<<sgrid, 256>>>(HID);
    }
    tanhdot<<<(NN + 1) / 2, 256>>>(ba1, Wa2, ba2);

    init_pool<<<(NG * HID + 255) / 256, 256>>>();
    segmax_kernel<<<(NN + 255) / 256, 256>>>();
    expsum_kernel<<<(NN + 255) / 256, 256>>>();
    weights_kernel<<<(NN + 255) / 256, 256>>>();
    pooled_kernel<<<(NN + 511) / 512, 256>>>();
    classifier_kernel<<<NG, 128>>>(Wc1, bc1, Wc2, bc2, out);
}